// round 5
// baseline (speedup 1.0000x reference)
#include <cuda_runtime.h>
#include <cuda_fp16.h>

// ---------------- problem constants (fixed by the dataset) ----------------
#define NN   100000     // nodes
#define NE   1600000    // edges
#define NGR  256        // graphs
#define NF   64         // node feat
#define NF2  128        // 2*NF
#define EFB  40         // rbf bins
#define NL   3          // layers
#define NAT  95         // atom types
#define NAF  200        // atom feat
#define TAB  8192       // e_lin nearest-lookup intervals over [0,8]
#define BN_EPS 1e-5f

// ---------------- persistent device scratch (no runtime allocation) -------
__device__ float  g_x   [NN * NF];          // node features (fp32)
__device__ __half g_hs  [NN * NF2];         // x @ W_src + b   (fp16)
__device__ __half g_hd  [NN * NF2];         // x @ W_dst + b   (fp16)
__device__ float  g_h   [NN * NF];          // scattered messages (fp32 accum)
__device__ __half g_m   [NE * NF2];         // cached pre-BN messages (fp16)
__device__ __half g_tab [(TAB + 1) * NF2];  // e_lin(d) nearest table (fp16)
__device__ float  g_emb [NAT * NF];         // atom_table @ W_embed + b
__device__ float  g_esum[NF2];
__device__ float  g_esq [NF2];
__device__ float  g_AB  [2 * NF2];          // folded BN: A*m+B
__device__ float  g_nsum[NF];
__device__ float  g_nsq [NF];
__device__ float  g_pool[NGR * NF];
__device__ float  g_cnt [NGR];

// ---------------- helpers -------------------------------------------------
__device__ __forceinline__ float sp_f(float x) {   // softplus
    return fmaxf(x, 0.0f) + __logf(1.0f + __expf(-fabsf(x)));
}
__device__ __forceinline__ float sig_f(float x) {
    return __fdividef(1.0f, 1.0f + __expf(-x));
}
__device__ __forceinline__ void mma16816(float c[4],
                                         unsigned a0, unsigned a1, unsigned a2, unsigned a3,
                                         unsigned b0, unsigned b1) {
    asm volatile(
        "mma.sync.aligned.m16n8k16.row.col.f32.f16.f16.f32 "
        "{%0,%1,%2,%3}, {%4,%5,%6,%7}, {%8,%9}, {%0,%1,%2,%3};\n"
        : "+f"(c[0]), "+f"(c[1]), "+f"(c[2]), "+f"(c[3])
        : "r"(a0), "r"(a1), "r"(a2), "r"(a3), "r"(b0), "r"(b1));
}

// --------------- 0a: fold atom featurizer + embedding into [95,64] --------
__global__ void k_emb(const float* __restrict__ at, const float* __restrict__ W,
                      const float* __restrict__ b) {
    int a = blockIdx.x, c = threadIdx.x;               // 95 blocks x 64 threads
    float acc = b[c];
    for (int k = 0; k < NAF; ++k)
        acc += at[a * NAF + k] * W[k * NF + c];
    g_emb[a * NF + c] = acc;
}

// --------------- 0b: x[n] = emb[type[n]] ----------------------------------
__global__ void k_gather_x(const int* __restrict__ types) {
    int i = blockIdx.x * blockDim.x + threadIdx.x;
    const int total = NN * (NF / 4);
    for (; i < total; i += gridDim.x * blockDim.x) {
        int n = i >> 4, j = i & 15;
        int t = __ldg(&types[n]);
        reinterpret_cast<float4*>(g_x)[i] =
            reinterpret_cast<const float4*>(g_emb)[t * (NF / 4) + j];
    }
}

// --------------- per-layer: build e_lin(d) table (fp16), 4 rows / block ---
__global__ void k_tab(const float* __restrict__ We, const float* __restrict__ be, int l) {
    __shared__ float phi[4][EFB];
    const int c = threadIdx.x;                          // 128 threads
    const int r0 = blockIdx.x * 4;
    if (c < EFB) {
        float ctr = c * (8.0f / 39.0f);                 // linspace(0,8,40)
#pragma unroll
        for (int r = 0; r < 4; ++r) {
            float x = (r0 + r) * (8.0f / TAB) - ctr;
            phi[r][c] = expf(-4.875f * x * x);          // gamma = 39/8
        }
    }
    __syncthreads();
    const float* W = We + l * EFB * NF2;
    const float bb = be[l * NF2 + c];
#pragma unroll
    for (int r = 0; r < 4; ++r) {
        if (r0 + r > TAB) break;
        float acc = bb;
#pragma unroll
        for (int k = 0; k < EFB; ++k)
            acc += phi[r][k] * W[k * NF2 + c];
        g_tab[(r0 + r) * NF2 + c] = __float2half_rn(acc);
    }
    if (blockIdx.x == 0) { g_esum[c] = 0.0f; g_esq[c] = 0.0f; }  // fused zeroing
}

// --------------- one-time zero of g_h -------------------------------------
__global__ void k_zero_h() {
    int i = blockIdx.x * blockDim.x + threadIdx.x;
    const int total = NN * (NF / 4);
    float4 z = make_float4(0.f, 0.f, 0.f, 0.f);
    for (; i < total; i += gridDim.x * blockDim.x)
        reinterpret_cast<float4*>(g_h)[i] = z;
}
__global__ void k_pool_zero() {
    int i = blockIdx.x * blockDim.x + threadIdx.x;      // 65*256 = 16640
    if (i < NGR * NF) g_pool[i] = 0.0f;
    else if (i < NGR * NF + NGR) g_cnt[i - NGR * NF] = 0.0f;
}

// --------------- node GEMM via tensor cores: H = fp16(x @ W + b) ----------
// block: 256 thr = 8 warps; tile 128 nodes x 128 cols; warps: 4 M-split x 2 N-split
__global__ __launch_bounds__(256) void k_node_gemm(
    const float* __restrict__ Wsrc, const float* __restrict__ bsrc,
    const float* __restrict__ Wdst, const float* __restrict__ bdst, int l) {
    const float* W = (blockIdx.y == 0 ? Wsrc : Wdst) + l * NF * NF2;
    const float* b = (blockIdx.y == 0 ? bsrc : bdst) + l * NF2;
    __half*      H = (blockIdx.y == 0 ? g_hs : g_hd);

    __shared__ __half xs[128 * 72];      // x tile  [row][k], stride 72 (conflict-free)
    __shared__ __half wt[128 * 72];      // W^T     [n][k],   stride 72

    const int tid = threadIdx.x;
    const int nb = blockIdx.x * 128;

#pragma unroll
    for (int i = 0; i < 32; ++i) {                      // W [64][128] -> wt[n][k]
        int idx = i * 256 + tid;
        int k = idx >> 7, n = idx & 127;
        wt[n * 72 + k] = __float2half_rn(W[idx]);
    }
#pragma unroll
    for (int i = 0; i < 16; ++i) {                      // x rows -> xs (fp32->fp16)
        int idx = i * 256 + tid;                        // 0..4095
        int row = idx >> 5, cp = idx & 31;
        int gr = nb + row; if (gr >= NN) gr = NN - 1;
        float2 v = *reinterpret_cast<const float2*>(g_x + gr * NF + cp * 2);
        *reinterpret_cast<__half2*>(&xs[row * 72 + cp * 2]) = __floats2half2_rn(v.x, v.y);
    }
    __syncthreads();

    const int w = tid >> 5, lane = tid & 31;
    const int m0 = (w & 3) * 32, n0 = (w >> 2) * 64;
    const int lr = lane >> 2, lc = (lane & 3) * 2;

    float c[2][8][4];
#pragma unroll
    for (int mt = 0; mt < 2; ++mt)
#pragma unroll
        for (int nt = 0; nt < 8; ++nt)
            c[mt][nt][0] = c[mt][nt][1] = c[mt][nt][2] = c[mt][nt][3] = 0.0f;

#pragma unroll
    for (int ks = 0; ks < 4; ++ks) {
        const int kk = ks * 16 + lc;
        unsigned bf[8][2];
#pragma unroll
        for (int nt = 0; nt < 8; ++nt) {
            int n = n0 + nt * 8 + lr;
            bf[nt][0] = *reinterpret_cast<unsigned*>(&wt[n * 72 + kk]);
            bf[nt][1] = *reinterpret_cast<unsigned*>(&wt[n * 72 + kk + 8]);
        }
#pragma unroll
        for (int mt = 0; mt < 2; ++mt) {
            int r = m0 + mt * 16 + lr;
            unsigned a0 = *reinterpret_cast<unsigned*>(&xs[r * 72 + kk]);
            unsigned a1 = *reinterpret_cast<unsigned*>(&xs[(r + 8) * 72 + kk]);
            unsigned a2 = *reinterpret_cast<unsigned*>(&xs[r * 72 + kk + 8]);
            unsigned a3 = *reinterpret_cast<unsigned*>(&xs[(r + 8) * 72 + kk + 8]);
#pragma unroll
            for (int nt = 0; nt < 8; ++nt)
                mma16816(c[mt][nt], a0, a1, a2, a3, bf[nt][0], bf[nt][1]);
        }
    }

#pragma unroll
    for (int nt = 0; nt < 8; ++nt) {
        int n = n0 + nt * 8 + lc;
        float2 bv = *reinterpret_cast<const float2*>(b + n);
#pragma unroll
        for (int mt = 0; mt < 2; ++mt) {
            int r = nb + m0 + mt * 16 + lr;
            __half2 h01 = __floats2half2_rn(c[mt][nt][0] + bv.x, c[mt][nt][1] + bv.y);
            __half2 h23 = __floats2half2_rn(c[mt][nt][2] + bv.x, c[mt][nt][3] + bv.y);
            if (r < NN)     *reinterpret_cast<__half2*>(H + r * NF2 + n) = h01;
            if (r + 8 < NN) *reinterpret_cast<__half2*>(H + (r + 8) * NF2 + n) = h23;
        }
    }
}

// --------------- pass A: gather, build m, cache it, accumulate stats ------
// lanes 0..15 edge e, lanes 16..31 edge e+1; sub-lane t owns 8 channels
__global__ __launch_bounds__(256) void k_edge_stats(const int* __restrict__ src,
                                                    const int* __restrict__ dst,
                                                    const float* __restrict__ dist) {
    const int lane = threadIdx.x & 31;
    const int half = lane >> 4;
    const int t    = lane & 15;
    const int wid  = (blockIdx.x * blockDim.x + threadIdx.x) >> 5;
    const int nw   = (gridDim.x * blockDim.x) >> 5;
    float2 s2[4], q2[4];
#pragma unroll
    for (int j = 0; j < 4; ++j) { s2[j] = make_float2(0, 0); q2[j] = make_float2(0, 0); }

    for (int e0 = wid * 2; e0 < NE; e0 += nw * 2) {
        const int e = e0 + half;
        int s = __ldg(&src[e]);
        int d = __ldg(&dst[e]);
        int i0 = min(__float2int_rn(__ldg(&dist[e]) * (TAB / 8.0f)), TAB);
        uint4 ua = reinterpret_cast<const uint4*>(g_hs)[s * 16 + t];
        uint4 ub = reinterpret_cast<const uint4*>(g_hd)[d * 16 + t];
        uint4 u0 = reinterpret_cast<const uint4*>(g_tab)[i0 * 16 + t];
        uint4 mo;
        __half2* po = reinterpret_cast<__half2*>(&mo);
#pragma unroll
        for (int j = 0; j < 4; ++j) {
            float2 va = __half22float2(reinterpret_cast<const __half2*>(&ua)[j]);
            float2 vb = __half22float2(reinterpret_cast<const __half2*>(&ub)[j]);
            float2 v0 = __half22float2(reinterpret_cast<const __half2*>(&u0)[j]);
            __half2 hq = __floats2half2_rn(va.x + vb.x + v0.x, va.y + vb.y + v0.y);
            po[j] = hq;
            float2 fq = __half22float2(hq);           // stats on quantized values
            s2[j].x += fq.x;        s2[j].y += fq.y;
            q2[j].x += fq.x * fq.x; q2[j].y += fq.y * fq.y;
        }
        reinterpret_cast<uint4*>(g_m)[e * 16 + t] = mo;   // coalesced 256B/edge
    }
    __shared__ float ss[NF2], sq[NF2];
    if (threadIdx.x < NF2) { ss[threadIdx.x] = 0.0f; sq[threadIdx.x] = 0.0f; }
    __syncthreads();
#pragma unroll
    for (int j = 0; j < 4; ++j) {
        atomicAdd(&ss[t * 8 + 2 * j],     s2[j].x);
        atomicAdd(&ss[t * 8 + 2 * j + 1], s2[j].y);
        atomicAdd(&sq[t * 8 + 2 * j],     q2[j].x);
        atomicAdd(&sq[t * 8 + 2 * j + 1], q2[j].y);
    }
    __syncthreads();
    if (threadIdx.x < NF2) {
        atomicAdd(&g_esum[threadIdx.x], ss[threadIdx.x]);
        atomicAdd(&g_esq [threadIdx.x], sq[threadIdx.x]);
    }
}

// --------------- fold BN into y = A*m + B (+ zero node-stat accums) -------
__global__ void k_finalize(const float* __restrict__ gm, const float* __restrict__ bm, int l) {
    int c = threadIdx.x;                                // 128
    float mean = g_esum[c] * (1.0f / NE);
    float var  = fmaxf(g_esq[c] * (1.0f / NE) - mean * mean, 0.0f);
    float A = gm[l * NF2 + c] * rsqrtf(var + BN_EPS);
    g_AB[c]       = A;
    g_AB[NF2 + c] = bm[l * NF2 + c] - mean * A;
    if (c < NF) { g_nsum[c] = 0.0f; g_nsq[c] = 0.0f; }  // fused zeroing
}

// --------------- pass B: stream m, normalize, gate, scatter to dst --------
__global__ __launch_bounds__(256) void k_edge_apply(const int* __restrict__ dst) {
    const int lane = threadIdx.x & 31;
    const int half = lane >> 4;
    const int t    = lane & 15;
    const int wid  = (blockIdx.x * blockDim.x + threadIdx.x) >> 5;
    const int nw   = (gridDim.x * blockDim.x) >> 5;

    const float4 A0 = reinterpret_cast<const float4*>(g_AB)[t * 2];
    const float4 A1 = reinterpret_cast<const float4*>(g_AB)[t * 2 + 1];
    const float4 B0 = reinterpret_cast<const float4*>(g_AB + NF2)[t * 2];
    const float4 B1 = reinterpret_cast<const float4*>(g_AB + NF2)[t * 2 + 1];

    for (int e0 = wid * 2; e0 < NE; e0 += nw * 2) {
        const int e = e0 + half;
        int dd = __ldg(&dst[e]);
        uint4 um = reinterpret_cast<const uint4*>(g_m)[e * 16 + t];
        float2 m0 = __half22float2(reinterpret_cast<const __half2*>(&um)[0]);
        float2 m1 = __half22float2(reinterpret_cast<const __half2*>(&um)[1]);
        float2 m2 = __half22float2(reinterpret_cast<const __half2*>(&um)[2]);
        float2 m3 = __half22float2(reinterpret_cast<const __half2*>(&um)[3]);
        float y[8];
        y[0] = A0.x * m0.x + B0.x;  y[1] = A0.y * m0.y + B0.y;
        y[2] = A0.z * m1.x + B0.z;  y[3] = A0.w * m1.y + B0.w;
        y[4] = A1.x * m2.x + B1.x;  y[5] = A1.y * m2.y + B1.y;
        y[6] = A1.z * m3.x + B1.z;  y[7] = A1.w * m3.y + B1.w;
        float p[8];
#pragma unroll
        for (int j = 0; j < 8; ++j)
            p[j] = __shfl_down_sync(0xffffffffu, y[j], 8);
        if (t < 8) {
            float4 o0, o1;
            o0.x = sig_f(y[0]) * sp_f(p[0]); o0.y = sig_f(y[1]) * sp_f(p[1]);
            o0.z = sig_f(y[2]) * sp_f(p[2]); o0.w = sig_f(y[3]) * sp_f(p[3]);
            o1.x = sig_f(y[4]) * sp_f(p[4]); o1.y = sig_f(y[5]) * sp_f(p[5]);
            o1.z = sig_f(y[6]) * sp_f(p[6]); o1.w = sig_f(y[7]) * sp_f(p[7]);
            float* base = g_h + dd * NF + t * 8;
            atomicAdd(reinterpret_cast<float4*>(base),     o0);
            atomicAdd(reinterpret_cast<float4*>(base + 4), o1);
        }
    }
}

// --------------- node BN stats --------------------------------------------
__global__ __launch_bounds__(256) void k_node_stats() {
    const int c = threadIdx.x & 63;
    int n = (blockIdx.x * blockDim.x + threadIdx.x) >> 6;
    const int stride = (gridDim.x * blockDim.x) >> 6;
    float s = 0.0f, q = 0.0f;
    for (; n < NN; n += stride) {
        float v = g_h[n * NF + c];
        s += v; q += v * v;
    }
    __shared__ float ss[NF], sq[NF];
    if (threadIdx.x < NF) { ss[threadIdx.x] = 0.0f; sq[threadIdx.x] = 0.0f; }
    __syncthreads();
    atomicAdd(&ss[c], s);
    atomicAdd(&sq[c], q);
    __syncthreads();
    if (threadIdx.x < NF) {
        atomicAdd(&g_nsum[threadIdx.x], ss[threadIdx.x]);
        atomicAdd(&g_nsq [threadIdx.x], sq[threadIdx.x]);
    }
}

// --------------- x = softplus(x + BN(h)); re-zero g_h in place ------------
__global__ __launch_bounds__(256) void k_node_update(const float* __restrict__ gb,
                                                     const float* __restrict__ bb, int l) {
    int i = blockIdx.x * blockDim.x + threadIdx.x;
    const int total = NN * NF;
    for (; i < total; i += gridDim.x * blockDim.x) {
        int c = i & 63;
        float mean = g_nsum[c] * (1.0f / NN);
        float var  = fmaxf(g_nsq[c] * (1.0f / NN) - mean * mean, 0.0f);
        float A = gb[l * NF + c] * rsqrtf(var + BN_EPS);
        float B = bb[l * NF + c] - mean * A;
        float v = g_x[i] + A * g_h[i] + B;
        g_h[i] = 0.0f;                                   // ready for next layer
        g_x[i] = sp_f(v);
    }
}

// --------------- readout --------------------------------------------------
__global__ __launch_bounds__(256) void k_pool(const int* __restrict__ gid) {
    const int lane = threadIdx.x & 31;
    int w = (blockIdx.x * blockDim.x + threadIdx.x) >> 5;
    const int nw = (gridDim.x * blockDim.x) >> 5;
    for (int n = w; n < NN; n += nw) {
        int g = __ldg(&gid[n]);
        if (lane < 16) {
            float4 v = reinterpret_cast<const float4*>(g_x + n * NF)[lane];
            atomicAdd(reinterpret_cast<float4*>(g_pool + g * NF + lane * 4), v);
        } else if (lane == 16) {
            atomicAdd(&g_cnt[g], 1.0f);
        }
    }
}
__global__ void k_div(float* __restrict__ out) {
    int i = blockIdx.x * blockDim.x + threadIdx.x;      // 64*256 = 16384
    if (i < NGR * NF)
        out[i] = g_pool[i] / fmaxf(g_cnt[i >> 6], 1.0f);
}

// ---------------- launcher ------------------------------------------------
extern "C" void kernel_launch(void* const* d_in, const int* in_sizes, int n_in,
                              void* d_out, int out_size) {
    const int*   atom_types = (const int*)  d_in[0];
    const float* distances  = (const float*)d_in[1];
    const int*   src        = (const int*)  d_in[2];
    const int*   dst        = (const int*)  d_in[3];
    const int*   gid        = (const int*)  d_in[4];
    const int base = (in_sizes[5] == 1) ? 6 : 5;   // n_graphs may be materialized
    const float* atom_table = (const float*)d_in[base + 0];
    const float* W_embed    = (const float*)d_in[base + 1];
    const float* b_embed    = (const float*)d_in[base + 2];
    const float* W_src      = (const float*)d_in[base + 3];
    const float* b_src      = (const float*)d_in[base + 4];
    const float* W_dst      = (const float*)d_in[base + 5];
    const float* b_dst      = (const float*)d_in[base + 6];
    const float* W_edge     = (const float*)d_in[base + 7];
    const float* b_edge     = (const float*)d_in[base + 8];
    const float* g_msg      = (const float*)d_in[base + 9];
    const float* beta_msg   = (const float*)d_in[base + 10];
    const float* g_bn       = (const float*)d_in[base + 11];
    const float* beta_bn    = (const float*)d_in[base + 12];
    float* out = (float*)d_out;

    k_emb<<<NAT, NF>>>(atom_table, W_embed, b_embed);
    k_gather_x<<<1024, 256>>>(atom_types);
    k_zero_h<<<1024, 256>>>();                           // one-time; update re-zeroes

    for (int l = 0; l < NL; ++l) {
        k_tab<<<(TAB + 4) / 4, NF2>>>(W_edge, b_edge, l);   // also zeroes edge stats
        k_node_gemm<<<dim3((NN + 127) / 128, 2), 256>>>(W_src, b_src, W_dst, b_dst, l);
        k_edge_stats<<<2048, 256>>>(src, dst, distances);
        k_finalize<<<1, NF2>>>(g_msg, beta_msg, l);         // also zeroes node stats
        k_edge_apply<<<2048, 256>>>(dst);
        k_node_stats<<<512, 256>>>();
        k_node_update<<<1024, 256>>>(g_bn, beta_bn, l);
    }

    k_pool_zero<<<65, 256>>>();
    k_pool<<<512, 256>>>(gid);
    k_div<<<64, 256>>>(out);
}

// round 7
// speedup vs baseline: 1.0017x; 1.0017x over previous
#include <cuda_runtime.h>
#include <cuda_fp16.h>

// ---------------- problem constants (fixed by the dataset) ----------------
#define NN   100000     // nodes
#define NE   1600000    // edges
#define NGR  256        // graphs
#define NF   64         // node feat
#define NF2  128        // 2*NF
#define EFB  40         // rbf bins
#define NL   3          // layers
#define NAT  95         // atom types
#define NAF  200        // atom feat
#define TAB  8192       // e_lin nearest-lookup intervals over [0,8]
#define BN_EPS 1e-5f

// ---------------- persistent device scratch (no runtime allocation) -------
__device__ float  g_x   [NN * NF];          // node features (fp32)
__device__ __half g_hs  [NN * NF2];         // x @ W_src + b   (fp16)
__device__ __half g_hd  [NN * NF2];         // x @ W_dst + b   (fp16)
__device__ float  g_h   [NN * NF];          // scattered messages (fp32 accum)
__device__ __half g_tab [(TAB + 1) * NF2];  // e_lin(d) nearest table (fp16)
__device__ float  g_emb [NAT * NF];         // atom_table @ W_embed + b
__device__ float  g_esum[NF2];
__device__ float  g_esq [NF2];
__device__ float  g_AB  [2 * NF2];          // folded BN: A*m+B
__device__ float  g_nsum[NF];
__device__ float  g_nsq [NF];
__device__ float  g_pool[NGR * NF];
__device__ float  g_cnt [NGR];

// ---------------- helpers -------------------------------------------------
__device__ __forceinline__ float sp_f(float x) {   // softplus
    return fmaxf(x, 0.0f) + __logf(1.0f + __expf(-fabsf(x)));
}
__device__ __forceinline__ float sig_f(float x) {
    return __fdividef(1.0f, 1.0f + __expf(-x));
}
__device__ __forceinline__ void mma16816(float c[4],
                                         unsigned a0, unsigned a1, unsigned a2, unsigned a3,
                                         unsigned b0, unsigned b1) {
    asm volatile(
        "mma.sync.aligned.m16n8k16.row.col.f32.f16.f16.f32 "
        "{%0,%1,%2,%3}, {%4,%5,%6,%7}, {%8,%9}, {%0,%1,%2,%3};\n"
        : "+f"(c[0]), "+f"(c[1]), "+f"(c[2]), "+f"(c[3])
        : "r"(a0), "r"(a1), "r"(a2), "r"(a3), "r"(b0), "r"(b1));
}

// --------------- 0a: fold atom featurizer + embedding into [95,64] --------
__global__ void k_emb(const float* __restrict__ at, const float* __restrict__ W,
                      const float* __restrict__ b) {
    int a = blockIdx.x, c = threadIdx.x;               // 95 blocks x 64 threads
    float acc = b[c];
    for (int k = 0; k < NAF; ++k)
        acc += at[a * NAF + k] * W[k * NF + c];
    g_emb[a * NF + c] = acc;
}

// --------------- 0b: x[n] = emb[type[n]] ----------------------------------
__global__ void k_gather_x(const int* __restrict__ types) {
    int i = blockIdx.x * blockDim.x + threadIdx.x;
    const int total = NN * (NF / 4);
    for (; i < total; i += gridDim.x * blockDim.x) {
        int n = i >> 4, j = i & 15;
        int t = __ldg(&types[n]);
        reinterpret_cast<float4*>(g_x)[i] =
            reinterpret_cast<const float4*>(g_emb)[t * (NF / 4) + j];
    }
}

// --------------- per-layer: build e_lin(d) table (fp16), 4 rows / block ---
__global__ void k_tab(const float* __restrict__ We, const float* __restrict__ be, int l) {
    __shared__ float phi[4][EFB];
    const int c = threadIdx.x;                          // 128 threads
    const int r0 = blockIdx.x * 4;
    if (c < EFB) {
        float ctr = c * (8.0f / 39.0f);                 // linspace(0,8,40)
#pragma unroll
        for (int r = 0; r < 4; ++r) {
            float x = (r0 + r) * (8.0f / TAB) - ctr;
            phi[r][c] = expf(-4.875f * x * x);          // gamma = 39/8
        }
    }
    __syncthreads();
    const float* W = We + l * EFB * NF2;
    const float bb = be[l * NF2 + c];
#pragma unroll
    for (int r = 0; r < 4; ++r) {
        if (r0 + r > TAB) break;
        float acc = bb;
#pragma unroll
        for (int k = 0; k < EFB; ++k)
            acc += phi[r][k] * W[k * NF2 + c];
        g_tab[(r0 + r) * NF2 + c] = __float2half_rn(acc);
    }
    if (blockIdx.x == 0) { g_esum[c] = 0.0f; g_esq[c] = 0.0f; }  // fused zeroing
}

// --------------- one-time zero of g_h -------------------------------------
__global__ void k_zero_h() {
    int i = blockIdx.x * blockDim.x + threadIdx.x;
    const int total = NN * (NF / 4);
    float4 z = make_float4(0.f, 0.f, 0.f, 0.f);
    for (; i < total; i += gridDim.x * blockDim.x)
        reinterpret_cast<float4*>(g_h)[i] = z;
}
__global__ void k_pool_zero() {
    int i = blockIdx.x * blockDim.x + threadIdx.x;      // 65*256 = 16640
    if (i < NGR * NF) g_pool[i] = 0.0f;
    else if (i < NGR * NF + NGR) g_cnt[i - NGR * NF] = 0.0f;
}

// --------------- node GEMM via tensor cores: H = fp16(x @ W + b) ----------
// block: 256 thr = 8 warps; tile 128 nodes x 128 cols; warps: 4 M-split x 2 N-split
__global__ __launch_bounds__(256) void k_node_gemm(
    const float* __restrict__ Wsrc, const float* __restrict__ bsrc,
    const float* __restrict__ Wdst, const float* __restrict__ bdst, int l) {
    const float* W = (blockIdx.y == 0 ? Wsrc : Wdst) + l * NF * NF2;
    const float* b = (blockIdx.y == 0 ? bsrc : bdst) + l * NF2;
    __half*      H = (blockIdx.y == 0 ? g_hs : g_hd);

    __shared__ __half xs[128 * 72];      // x tile  [row][k], stride 72 (conflict-free)
    __shared__ __half wt[128 * 72];      // W^T     [n][k],   stride 72

    const int tid = threadIdx.x;
    const int nb = blockIdx.x * 128;

#pragma unroll
    for (int i = 0; i < 32; ++i) {                      // W [64][128] -> wt[n][k]
        int idx = i * 256 + tid;
        int k = idx >> 7, n = idx & 127;
        wt[n * 72 + k] = __float2half_rn(W[idx]);
    }
#pragma unroll
    for (int i = 0; i < 16; ++i) {                      // x rows -> xs (fp32->fp16)
        int idx = i * 256 + tid;                        // 0..4095
        int row = idx >> 5, cp = idx & 31;
        int gr = nb + row; if (gr >= NN) gr = NN - 1;
        float2 v = *reinterpret_cast<const float2*>(g_x + gr * NF + cp * 2);
        *reinterpret_cast<__half2*>(&xs[row * 72 + cp * 2]) = __floats2half2_rn(v.x, v.y);
    }
    __syncthreads();

    const int w = tid >> 5, lane = tid & 31;
    const int m0 = (w & 3) * 32, n0 = (w >> 2) * 64;
    const int lr = lane >> 2, lc = (lane & 3) * 2;

    float c[2][8][4];
#pragma unroll
    for (int mt = 0; mt < 2; ++mt)
#pragma unroll
        for (int nt = 0; nt < 8; ++nt)
            c[mt][nt][0] = c[mt][nt][1] = c[mt][nt][2] = c[mt][nt][3] = 0.0f;

#pragma unroll
    for (int ks = 0; ks < 4; ++ks) {
        const int kk = ks * 16 + lc;
        unsigned bf[8][2];
#pragma unroll
        for (int nt = 0; nt < 8; ++nt) {
            int n = n0 + nt * 8 + lr;
            bf[nt][0] = *reinterpret_cast<unsigned*>(&wt[n * 72 + kk]);
            bf[nt][1] = *reinterpret_cast<unsigned*>(&wt[n * 72 + kk + 8]);
        }
#pragma unroll
        for (int mt = 0; mt < 2; ++mt) {
            int r = m0 + mt * 16 + lr;
            unsigned a0 = *reinterpret_cast<unsigned*>(&xs[r * 72 + kk]);
            unsigned a1 = *reinterpret_cast<unsigned*>(&xs[(r + 8) * 72 + kk]);
            unsigned a2 = *reinterpret_cast<unsigned*>(&xs[r * 72 + kk + 8]);
            unsigned a3 = *reinterpret_cast<unsigned*>(&xs[(r + 8) * 72 + kk + 8]);
#pragma unroll
            for (int nt = 0; nt < 8; ++nt)
                mma16816(c[mt][nt], a0, a1, a2, a3, bf[nt][0], bf[nt][1]);
        }
    }

#pragma unroll
    for (int nt = 0; nt < 8; ++nt) {
        int n = n0 + nt * 8 + lc;
        float2 bv = *reinterpret_cast<const float2*>(b + n);
#pragma unroll
        for (int mt = 0; mt < 2; ++mt) {
            int r = nb + m0 + mt * 16 + lr;
            __half2 h01 = __floats2half2_rn(c[mt][nt][0] + bv.x, c[mt][nt][1] + bv.y);
            __half2 h23 = __floats2half2_rn(c[mt][nt][2] + bv.x, c[mt][nt][3] + bv.y);
            if (r < NN)     *reinterpret_cast<__half2*>(H + r * NF2 + n) = h01;
            if (r + 8 < NN) *reinterpret_cast<__half2*>(H + (r + 8) * NF2 + n) = h23;
        }
    }
}

// --------------- per-edge message recompute (8 channels / lane) -----------
// lanes 0..15 edge e, lanes 16..31 edge e+1; sub-lane t owns channels 8t..8t+7
struct M8 { float2 v[4]; };

__device__ __forceinline__ M8 edge_m8(int e, int t,
                                      const int* __restrict__ src,
                                      const int* __restrict__ dst,
                                      const float* __restrict__ dist,
                                      int* outd) {
    int s = __ldg(&src[e]);
    int d = __ldg(&dst[e]);
    int i0 = min(__float2int_rn(__ldg(&dist[e]) * (TAB / 8.0f)), TAB);
    uint4 ua = reinterpret_cast<const uint4*>(g_hs)[s * 16 + t];
    uint4 ub = reinterpret_cast<const uint4*>(g_hd)[d * 16 + t];
    uint4 u0 = reinterpret_cast<const uint4*>(g_tab)[i0 * 16 + t];
    M8 m;
#pragma unroll
    for (int j = 0; j < 4; ++j) {
        float2 va = __half22float2(reinterpret_cast<const __half2*>(&ua)[j]);
        float2 vb = __half22float2(reinterpret_cast<const __half2*>(&ub)[j]);
        float2 v0 = __half22float2(reinterpret_cast<const __half2*>(&u0)[j]);
        m.v[j].x = va.x + vb.x + v0.x;
        m.v[j].y = va.y + vb.y + v0.y;
    }
    *outd = d;
    return m;
}

// --------------- pass A: per-channel sum/sumsq of m over edges ------------
__global__ __launch_bounds__(256) void k_edge_stats(const int* __restrict__ src,
                                                    const int* __restrict__ dst,
                                                    const float* __restrict__ dist) {
    const int lane = threadIdx.x & 31;
    const int half = lane >> 4;
    const int t    = lane & 15;
    const int wid  = (blockIdx.x * blockDim.x + threadIdx.x) >> 5;
    const int nw   = (gridDim.x * blockDim.x) >> 5;
    float2 s2[4], q2[4];
#pragma unroll
    for (int j = 0; j < 4; ++j) { s2[j] = make_float2(0, 0); q2[j] = make_float2(0, 0); }

    for (int e0 = wid * 2; e0 < NE; e0 += nw * 2) {
        int dd;
        M8 m = edge_m8(e0 + half, t, src, dst, dist, &dd);
#pragma unroll
        for (int j = 0; j < 4; ++j) {
            s2[j].x += m.v[j].x;            s2[j].y += m.v[j].y;
            q2[j].x += m.v[j].x * m.v[j].x; q2[j].y += m.v[j].y * m.v[j].y;
        }
    }
    __shared__ float ss[NF2], sq[NF2];
    if (threadIdx.x < NF2) { ss[threadIdx.x] = 0.0f; sq[threadIdx.x] = 0.0f; }
    __syncthreads();
#pragma unroll
    for (int j = 0; j < 4; ++j) {
        atomicAdd(&ss[t * 8 + 2 * j],     s2[j].x);
        atomicAdd(&ss[t * 8 + 2 * j + 1], s2[j].y);
        atomicAdd(&sq[t * 8 + 2 * j],     q2[j].x);
        atomicAdd(&sq[t * 8 + 2 * j + 1], q2[j].y);
    }
    __syncthreads();
    if (threadIdx.x < NF2) {
        atomicAdd(&g_esum[threadIdx.x], ss[threadIdx.x]);
        atomicAdd(&g_esq [threadIdx.x], sq[threadIdx.x]);
    }
}

// --------------- fold BN into y = A*m + B (+ zero node-stat accums) -------
__global__ void k_finalize(const float* __restrict__ gm, const float* __restrict__ bm, int l) {
    int c = threadIdx.x;                                // 128
    float mean = g_esum[c] * (1.0f / NE);
    float var  = fmaxf(g_esq[c] * (1.0f / NE) - mean * mean, 0.0f);
    float A = gm[l * NF2 + c] * rsqrtf(var + BN_EPS);
    g_AB[c]       = A;
    g_AB[NF2 + c] = bm[l * NF2 + c] - mean * A;
    if (c < NF) { g_nsum[c] = 0.0f; g_nsq[c] = 0.0f; }  // fused zeroing
}

// --------------- pass B: recompute m, normalize, gate, scatter ------------
__global__ __launch_bounds__(256) void k_edge_apply(const int* __restrict__ src,
                                                    const int* __restrict__ dst,
                                                    const float* __restrict__ dist) {
    const int lane = threadIdx.x & 31;
    const int half = lane >> 4;
    const int t    = lane & 15;
    const int wid  = (blockIdx.x * blockDim.x + threadIdx.x) >> 5;
    const int nw   = (gridDim.x * blockDim.x) >> 5;

    const float4 A0 = reinterpret_cast<const float4*>(g_AB)[t * 2];
    const float4 A1 = reinterpret_cast<const float4*>(g_AB)[t * 2 + 1];
    const float4 B0 = reinterpret_cast<const float4*>(g_AB + NF2)[t * 2];
    const float4 B1 = reinterpret_cast<const float4*>(g_AB + NF2)[t * 2 + 1];

    for (int e0 = wid * 2; e0 < NE; e0 += nw * 2) {
        int dd;
        M8 m = edge_m8(e0 + half, t, src, dst, dist, &dd);
        float y[8];
        y[0] = A0.x * m.v[0].x + B0.x;  y[1] = A0.y * m.v[0].y + B0.y;
        y[2] = A0.z * m.v[1].x + B0.z;  y[3] = A0.w * m.v[1].y + B0.w;
        y[4] = A1.x * m.v[2].x + B1.x;  y[5] = A1.y * m.v[2].y + B1.y;
        y[6] = A1.z * m.v[3].x + B1.z;  y[7] = A1.w * m.v[3].y + B1.w;
        // partner channels (c+64) live on sub-lane t+8 of the same half-warp
        float p[8];
#pragma unroll
        for (int j = 0; j < 8; ++j)
            p[j] = __shfl_down_sync(0xffffffffu, y[j], 8);
        if (t < 8) {
            float4 o0, o1;
            o0.x = sig_f(y[0]) * sp_f(p[0]); o0.y = sig_f(y[1]) * sp_f(p[1]);
            o0.z = sig_f(y[2]) * sp_f(p[2]); o0.w = sig_f(y[3]) * sp_f(p[3]);
            o1.x = sig_f(y[4]) * sp_f(p[4]); o1.y = sig_f(y[5]) * sp_f(p[5]);
            o1.z = sig_f(y[6]) * sp_f(p[6]); o1.w = sig_f(y[7]) * sp_f(p[7]);
            float* base = g_h + dd * NF + t * 8;
            atomicAdd(reinterpret_cast<float4*>(base),     o0);
            atomicAdd(reinterpret_cast<float4*>(base + 4), o1);
        }
    }
}

// --------------- node BN stats --------------------------------------------
__global__ __launch_bounds__(256) void k_node_stats() {
    const int c = threadIdx.x & 63;
    int n = (blockIdx.x * blockDim.x + threadIdx.x) >> 6;
    const int stride = (gridDim.x * blockDim.x) >> 6;
    float s = 0.0f, q = 0.0f;
    for (; n < NN; n += stride) {
        float v = g_h[n * NF + c];
        s += v; q += v * v;
    }
    __shared__ float ss[NF], sq[NF];
    if (threadIdx.x < NF) { ss[threadIdx.x] = 0.0f; sq[threadIdx.x] = 0.0f; }
    __syncthreads();
    atomicAdd(&ss[c], s);
    atomicAdd(&sq[c], q);
    __syncthreads();
    if (threadIdx.x < NF) {
        atomicAdd(&g_nsum[threadIdx.x], ss[threadIdx.x]);
        atomicAdd(&g_nsq [threadIdx.x], sq[threadIdx.x]);
    }
}

// --------------- x = softplus(x + BN(h)); re-zero g_h in place ------------
__global__ __launch_bounds__(256) void k_node_update(const float* __restrict__ gb,
                                                     const float* __restrict__ bb, int l) {
    int i = blockIdx.x * blockDim.x + threadIdx.x;
    const int total = NN * NF;
    for (; i < total; i += gridDim.x * blockDim.x) {
        int c = i & 63;
        float mean = g_nsum[c] * (1.0f / NN);
        float var  = fmaxf(g_nsq[c] * (1.0f / NN) - mean * mean, 0.0f);
        float A = gb[l * NF + c] * rsqrtf(var + BN_EPS);
        float B = bb[l * NF + c] - mean * A;
        float v = g_x[i] + A * g_h[i] + B;
        g_h[i] = 0.0f;                                   // ready for next layer
        g_x[i] = sp_f(v);
    }
}

// --------------- readout --------------------------------------------------
__global__ __launch_bounds__(256) void k_pool(const int* __restrict__ gid) {
    const int lane = threadIdx.x & 31;
    int w = (blockIdx.x * blockDim.x + threadIdx.x) >> 5;
    const int nw = (gridDim.x * blockDim.x) >> 5;
    for (int n = w; n < NN; n += nw) {
        int g = __ldg(&gid[n]);
        if (lane < 16) {
            float4 v = reinterpret_cast<const float4*>(g_x + n * NF)[lane];
            atomicAdd(reinterpret_cast<float4*>(g_pool + g * NF + lane * 4), v);
        } else if (lane == 16) {
            atomicAdd(&g_cnt[g], 1.0f);
        }
    }
}
__global__ void k_div(float* __restrict__ out) {
    int i = blockIdx.x * blockDim.x + threadIdx.x;      // 64*256 = 16384
    if (i < NGR * NF)
        out[i] = g_pool[i] / fmaxf(g_cnt[i >> 6], 1.0f);
}

// ---------------- launcher ------------------------------------------------
extern "C" void kernel_launch(void* const* d_in, const int* in_sizes, int n_in,
                              void* d_out, int out_size) {
    const int*   atom_types = (const int*)  d_in[0];
    const float* distances  = (const float*)d_in[1];
    const int*   src        = (const int*)  d_in[2];
    const int*   dst        = (const int*)  d_in[3];
    const int*   gid        = (const int*)  d_in[4];
    const int base = (in_sizes[5] == 1) ? 6 : 5;   // n_graphs may be materialized
    const float* atom_table = (const float*)d_in[base + 0];
    const float* W_embed    = (const float*)d_in[base + 1];
    const float* b_embed    = (const float*)d_in[base + 2];
    const float* W_src      = (const float*)d_in[base + 3];
    const float* b_src      = (const float*)d_in[base + 4];
    const float* W_dst      = (const float*)d_in[base + 5];
    const float* b_dst      = (const float*)d_in[base + 6];
    const float* W_edge     = (const float*)d_in[base + 7];
    const float* b_edge     = (const float*)d_in[base + 8];
    const float* g_msg      = (const float*)d_in[base + 9];
    const float* beta_msg   = (const float*)d_in[base + 10];
    const float* g_bn       = (const float*)d_in[base + 11];
    const float* beta_bn    = (const float*)d_in[base + 12];
    float* out = (float*)d_out;

    k_emb<<<NAT, NF>>>(atom_table, W_embed, b_embed);
    k_gather_x<<<1024, 256>>>(atom_types);
    k_zero_h<<<1024, 256>>>();                           // one-time; update re-zeroes

    for (int l = 0; l < NL; ++l) {
        k_tab<<<(TAB + 4) / 4, NF2>>>(W_edge, b_edge, l);   // also zeroes edge stats
        k_node_gemm<<<dim3((NN + 127) / 128, 2), 256>>>(W_src, b_src, W_dst, b_dst, l);
        k_edge_stats<<<2048, 256>>>(src, dst, distances);
        k_finalize<<<1, NF2>>>(g_msg, beta_msg, l);         // also zeroes node stats
        k_edge_apply<<<2048, 256>>>(src, dst, distances);
        k_node_stats<<<512, 256>>>();
        k_node_update<<<1024, 256>>>(g_bn, beta_bn, l);
    }

    k_pool_zero<<<65, 256>>>();
    k_pool<<<512, 256>>>(gid);
    k_div<<<64, 256>>>(out);
}

// round 9
// speedup vs baseline: 1.1892x; 1.1872x over previous
#include <cuda_runtime.h>
#include <cuda_fp16.h>

// ---------------- problem constants (fixed by the dataset) ----------------
#define NN   100000     // nodes
#define NE   1600000    // edges
#define NGR  256        // graphs
#define NF   64         // node feat
#define NF2  128        // 2*NF
#define EFB  40         // rbf bins
#define NL   3          // layers
#define NAT  95         // atom types
#define NAF  200        // atom feat
#define TAB  8192       // e_lin nearest-lookup intervals over [0,8]
#define BN_EPS 1e-5f

// ---------------- persistent device scratch (no runtime allocation) -------
__device__ float  g_x   [NN * NF];          // node features (fp32)
__device__ __half g_hs  [NN * NF2];         // x @ W_src + b   (fp16)
__device__ __half g_hd  [NN * NF2];         // x @ W_dst + b   (fp16)
__device__ float  g_h   [NN * NF];          // per-node aggregated messages
__device__ __half g_tab [(TAB + 1) * NF2];  // e_lin(d) nearest table (fp16)
__device__ float  g_emb [NAT * NF];         // atom_table @ W_embed + b
__device__ int    g_rowptr[NN + 1];         // CSR by dst
__device__ int    g_cursor[NN];             // counts, then scatter cursors
__device__ int    g_csr   [NE];             // packed: src | (bin<<17)
__device__ float  g_esum[NF2];
__device__ float  g_esq [NF2];
__device__ float  g_AB  [2 * NF2];          // folded BN: A*m+B
__device__ float  g_nsum[NF];
__device__ float  g_nsq [NF];
__device__ float  g_pool[NGR * NF];
__device__ float  g_cnt [NGR];

// ---------------- helpers -------------------------------------------------
__device__ __forceinline__ float sp_f(float x) {   // softplus
    return fmaxf(x, 0.0f) + __logf(1.0f + __expf(-fabsf(x)));
}
__device__ __forceinline__ float sig_f(float x) {
    return __fdividef(1.0f, 1.0f + __expf(-x));
}
__device__ __forceinline__ void mma16816(float c[4],
                                         unsigned a0, unsigned a1, unsigned a2, unsigned a3,
                                         unsigned b0, unsigned b1) {
    asm volatile(
        "mma.sync.aligned.m16n8k16.row.col.f32.f16.f16.f32 "
        "{%0,%1,%2,%3}, {%4,%5,%6,%7}, {%8,%9}, {%0,%1,%2,%3};\n"
        : "+f"(c[0]), "+f"(c[1]), "+f"(c[2]), "+f"(c[3])
        : "r"(a0), "r"(a1), "r"(a2), "r"(a3), "r"(b0), "r"(b1));
}

// --------------- 0a: fold atom featurizer + embedding into [95,64] --------
__global__ void k_emb(const float* __restrict__ at, const float* __restrict__ W,
                      const float* __restrict__ b) {
    int a = blockIdx.x, c = threadIdx.x;               // 95 blocks x 64 threads
    float acc = b[c];
    for (int k = 0; k < NAF; ++k)
        acc += at[a * NAF + k] * W[k * NF + c];
    g_emb[a * NF + c] = acc;
}

// --------------- 0b: x[n] = emb[type[n]] ----------------------------------
__global__ void k_gather_x(const int* __restrict__ types) {
    int i = blockIdx.x * blockDim.x + threadIdx.x;
    const int total = NN * (NF / 4);
    for (; i < total; i += gridDim.x * blockDim.x) {
        int n = i >> 4, j = i & 15;
        int t = __ldg(&types[n]);
        reinterpret_cast<float4*>(g_x)[i] =
            reinterpret_cast<const float4*>(g_emb)[t * (NF / 4) + j];
    }
}

// --------------- CSR build (one-time, reused for all layers) --------------
__global__ void k_csr_zero() {
    int i = blockIdx.x * blockDim.x + threadIdx.x;
    for (; i < NN; i += gridDim.x * blockDim.x) g_cursor[i] = 0;
}
__global__ void k_csr_hist(const int* __restrict__ dst) {
    int e = blockIdx.x * blockDim.x + threadIdx.x;
    for (; e < NE; e += gridDim.x * blockDim.x)
        atomicAdd(&g_cursor[__ldg(&dst[e])], 1);
}
// single-block Hillis-Steele scan over 100K counts -> rowptr (+cursor copy)
__global__ void k_scan() {
    __shared__ int s[1024];
    __shared__ int carry;
    const int tid = threadIdx.x;
    if (tid == 0) carry = 0;
    __syncthreads();
    for (int base = 0; base < NN; base += 1024) {
        int i = base + tid;
        int v = (i < NN) ? g_cursor[i] : 0;
        s[tid] = v;
        __syncthreads();
        for (int off = 1; off < 1024; off <<= 1) {
            int t = (tid >= off) ? s[tid - off] : 0;
            __syncthreads();
            s[tid] += t;
            __syncthreads();
        }
        int excl = carry + s[tid] - v;
        if (i < NN) { g_rowptr[i] = excl; g_cursor[i] = excl; }
        __syncthreads();
        if (tid == 0) carry += s[1023];
        __syncthreads();
    }
    if (tid == 0) g_rowptr[NN] = carry;    // == NE
}
__global__ void k_csr_scatter(const int* __restrict__ src, const int* __restrict__ dst,
                              const float* __restrict__ dist) {
    int e = blockIdx.x * blockDim.x + threadIdx.x;
    for (; e < NE; e += gridDim.x * blockDim.x) {
        int d = __ldg(&dst[e]);
        int pos = atomicAdd(&g_cursor[d], 1);
        int bin = min(__float2int_rn(__ldg(&dist[e]) * (TAB / 8.0f)), TAB);
        g_csr[pos] = __ldg(&src[e]) | (bin << 17);
    }
}

// --------------- per-layer: build e_lin(d) table (fp16), 4 rows / block ---
__global__ void k_tab(const float* __restrict__ We, const float* __restrict__ be, int l) {
    __shared__ float phi[4][EFB];
    const int c = threadIdx.x;                          // 128 threads
    const int r0 = blockIdx.x * 4;
    if (c < EFB) {
        float ctr = c * (8.0f / 39.0f);                 // linspace(0,8,40)
#pragma unroll
        for (int r = 0; r < 4; ++r) {
            float x = (r0 + r) * (8.0f / TAB) - ctr;
            phi[r][c] = expf(-4.875f * x * x);          // gamma = 39/8
        }
    }
    __syncthreads();
    const float* W = We + l * EFB * NF2;
    const float bb = be[l * NF2 + c];
#pragma unroll
    for (int r = 0; r < 4; ++r) {
        if (r0 + r > TAB) break;
        float acc = bb;
#pragma unroll
        for (int k = 0; k < EFB; ++k)
            acc += phi[r][k] * W[k * NF2 + c];
        g_tab[(r0 + r) * NF2 + c] = __float2half_rn(acc);
    }
    if (blockIdx.x == 0) { g_esum[c] = 0.0f; g_esq[c] = 0.0f; }  // fused zeroing
}

__global__ void k_pool_zero() {
    int i = blockIdx.x * blockDim.x + threadIdx.x;      // 65*256 = 16640
    if (i < NGR * NF) g_pool[i] = 0.0f;
    else if (i < NGR * NF + NGR) g_cnt[i - NGR * NF] = 0.0f;
}

// --------------- node GEMM via tensor cores: H = fp16(x @ W + b) ----------
__global__ __launch_bounds__(256) void k_node_gemm(
    const float* __restrict__ Wsrc, const float* __restrict__ bsrc,
    const float* __restrict__ Wdst, const float* __restrict__ bdst, int l) {
    const float* W = (blockIdx.y == 0 ? Wsrc : Wdst) + l * NF * NF2;
    const float* b = (blockIdx.y == 0 ? bsrc : bdst) + l * NF2;
    __half*      H = (blockIdx.y == 0 ? g_hs : g_hd);

    __shared__ __half xs[128 * 72];
    __shared__ __half wt[128 * 72];

    const int tid = threadIdx.x;
    const int nb = blockIdx.x * 128;

#pragma unroll
    for (int i = 0; i < 32; ++i) {                      // W [64][128] -> wt[n][k]
        int idx = i * 256 + tid;
        int k = idx >> 7, n = idx & 127;
        wt[n * 72 + k] = __float2half_rn(W[idx]);
    }
#pragma unroll
    for (int i = 0; i < 16; ++i) {                      // x rows -> xs
        int idx = i * 256 + tid;
        int row = idx >> 5, cp = idx & 31;
        int gr = nb + row; if (gr >= NN) gr = NN - 1;
        float2 v = *reinterpret_cast<const float2*>(g_x + gr * NF + cp * 2);
        *reinterpret_cast<__half2*>(&xs[row * 72 + cp * 2]) = __floats2half2_rn(v.x, v.y);
    }
    __syncthreads();

    const int w = tid >> 5, lane = tid & 31;
    const int m0 = (w & 3) * 32, n0 = (w >> 2) * 64;
    const int lr = lane >> 2, lc = (lane & 3) * 2;

    float c[2][8][4];
#pragma unroll
    for (int mt = 0; mt < 2; ++mt)
#pragma unroll
        for (int nt = 0; nt < 8; ++nt)
            c[mt][nt][0] = c[mt][nt][1] = c[mt][nt][2] = c[mt][nt][3] = 0.0f;

#pragma unroll
    for (int ks = 0; ks < 4; ++ks) {
        const int kk = ks * 16 + lc;
        unsigned bf[8][2];
#pragma unroll
        for (int nt = 0; nt < 8; ++nt) {
            int n = n0 + nt * 8 + lr;
            bf[nt][0] = *reinterpret_cast<unsigned*>(&wt[n * 72 + kk]);
            bf[nt][1] = *reinterpret_cast<unsigned*>(&wt[n * 72 + kk + 8]);
        }
#pragma unroll
        for (int mt = 0; mt < 2; ++mt) {
            int r = m0 + mt * 16 + lr;
            unsigned a0 = *reinterpret_cast<unsigned*>(&xs[r * 72 + kk]);
            unsigned a1 = *reinterpret_cast<unsigned*>(&xs[(r + 8) * 72 + kk]);
            unsigned a2 = *reinterpret_cast<unsigned*>(&xs[r * 72 + kk + 8]);
            unsigned a3 = *reinterpret_cast<unsigned*>(&xs[(r + 8) * 72 + kk + 8]);
#pragma unroll
            for (int nt = 0; nt < 8; ++nt)
                mma16816(c[mt][nt], a0, a1, a2, a3, bf[nt][0], bf[nt][1]);
        }
    }

#pragma unroll
    for (int nt = 0; nt < 8; ++nt) {
        int n = n0 + nt * 8 + lc;
        float2 bv = *reinterpret_cast<const float2*>(b + n);
#pragma unroll
        for (int mt = 0; mt < 2; ++mt) {
            int r = nb + m0 + mt * 16 + lr;
            __half2 h01 = __floats2half2_rn(c[mt][nt][0] + bv.x, c[mt][nt][1] + bv.y);
            __half2 h23 = __floats2half2_rn(c[mt][nt][2] + bv.x, c[mt][nt][3] + bv.y);
            if (r < NN)     *reinterpret_cast<__half2*>(H + r * NF2 + n) = h01;
            if (r + 8 < NN) *reinterpret_cast<__half2*>(H + (r + 8) * NF2 + n) = h23;
        }
    }
}

// --------------- pass A: CSR-ordered per-channel sum/sumsq of m -----------
// warp per node; hd loaded once; halves process 2 edges/step; sub-lane t: 8 ch
__global__ __launch_bounds__(256) void k_edge_stats() {
    const int lane = threadIdx.x & 31;
    const int half = lane >> 4;
    const int t    = lane & 15;
    int       wid  = (blockIdx.x * blockDim.x + threadIdx.x) >> 5;
    const int nw   = (gridDim.x * blockDim.x) >> 5;
    float2 s2[4], q2[4];
#pragma unroll
    for (int j = 0; j < 4; ++j) { s2[j] = make_float2(0, 0); q2[j] = make_float2(0, 0); }

    for (int n = wid; n < NN; n += nw) {
        const int e0 = __ldg(&g_rowptr[n]);
        const int e1 = __ldg(&g_rowptr[n + 1]);
        if (e0 == e1) continue;
        uint4 ub = reinterpret_cast<const uint4*>(g_hd)[n * 16 + t];
        float2 vb[4];
#pragma unroll
        for (int j = 0; j < 4; ++j)
            vb[j] = __half22float2(reinterpret_cast<const __half2*>(&ub)[j]);

        for (int es = e0; es < e1; es += 32) {
            int pk = (es + lane < e1) ? g_csr[es + lane] : 0;   // coalesced prefetch
            const int cnt = min(32, e1 - es);
            for (int j = 0; j < cnt; j += 2) {
                int myj = j + half;
                int pke = __shfl_sync(0xffffffffu, pk, myj);
                if (myj < cnt) {
                    int s   = pke & 0x1FFFF;
                    int bin = ((unsigned)pke) >> 17;
                    uint4 ua = reinterpret_cast<const uint4*>(g_hs)[s * 16 + t];
                    uint4 ut = reinterpret_cast<const uint4*>(g_tab)[bin * 16 + t];
#pragma unroll
                    for (int q = 0; q < 4; ++q) {
                        float2 va = __half22float2(reinterpret_cast<const __half2*>(&ua)[q]);
                        float2 vt = __half22float2(reinterpret_cast<const __half2*>(&ut)[q]);
                        float mx = va.x + vb[q].x + vt.x;
                        float my = va.y + vb[q].y + vt.y;
                        s2[q].x += mx;      s2[q].y += my;
                        q2[q].x += mx * mx; q2[q].y += my * my;
                    }
                }
            }
        }
    }
    __shared__ float ss[NF2], sq[NF2];
    if (threadIdx.x < NF2) { ss[threadIdx.x] = 0.0f; sq[threadIdx.x] = 0.0f; }
    __syncthreads();
#pragma unroll
    for (int j = 0; j < 4; ++j) {
        atomicAdd(&ss[t * 8 + 2 * j],     s2[j].x);
        atomicAdd(&ss[t * 8 + 2 * j + 1], s2[j].y);
        atomicAdd(&sq[t * 8 + 2 * j],     q2[j].x);
        atomicAdd(&sq[t * 8 + 2 * j + 1], q2[j].y);
    }
    __syncthreads();
    if (threadIdx.x < NF2) {
        atomicAdd(&g_esum[threadIdx.x], ss[threadIdx.x]);
        atomicAdd(&g_esq [threadIdx.x], sq[threadIdx.x]);
    }
}

// --------------- fold BN into y = A*m + B (+ zero node-stat accums) -------
__global__ void k_finalize(const float* __restrict__ gm, const float* __restrict__ bm, int l) {
    int c = threadIdx.x;                                // 128
    float mean = g_esum[c] * (1.0f / NE);
    float var  = fmaxf(g_esq[c] * (1.0f / NE) - mean * mean, 0.0f);
    float A = gm[l * NF2 + c] * rsqrtf(var + BN_EPS);
    g_AB[c]       = A;
    g_AB[NF2 + c] = bm[l * NF2 + c] - mean * A;
    if (c < NF) { g_nsum[c] = 0.0f; g_nsq[c] = 0.0f; }  // fused zeroing
}

// --------------- pass B: CSR gather, gate, per-node reg accumulate --------
// NO atomics: warp owns node n exclusively, stores h[n] with plain STG.
// Node BN stats fused (h is in registers).
__global__ __launch_bounds__(256) void k_edge_apply() {
    const int lane = threadIdx.x & 31;
    const int half = lane >> 4;
    const int t    = lane & 15;
    int       wid  = (blockIdx.x * blockDim.x + threadIdx.x) >> 5;
    const int nw   = (gridDim.x * blockDim.x) >> 5;

    const float4 A0 = reinterpret_cast<const float4*>(g_AB)[t * 2];
    const float4 A1 = reinterpret_cast<const float4*>(g_AB)[t * 2 + 1];
    const float4 B0 = reinterpret_cast<const float4*>(g_AB + NF2)[t * 2];
    const float4 B1 = reinterpret_cast<const float4*>(g_AB + NF2)[t * 2 + 1];

    float hsum[8], hsq[8];
#pragma unroll
    for (int i = 0; i < 8; ++i) { hsum[i] = 0.0f; hsq[i] = 0.0f; }

    for (int n = wid; n < NN; n += nw) {
        const int e0 = __ldg(&g_rowptr[n]);
        const int e1 = __ldg(&g_rowptr[n + 1]);

        float hacc[8];
#pragma unroll
        for (int i = 0; i < 8; ++i) hacc[i] = 0.0f;

        if (e0 != e1) {
            uint4 ub = reinterpret_cast<const uint4*>(g_hd)[n * 16 + t];
            float2 vb[4];
#pragma unroll
            for (int j = 0; j < 4; ++j)
                vb[j] = __half22float2(reinterpret_cast<const __half2*>(&ub)[j]);

            for (int es = e0; es < e1; es += 32) {
                int pk = (es + lane < e1) ? g_csr[es + lane] : 0;
                const int cnt = min(32, e1 - es);
                for (int j = 0; j < cnt; j += 2) {
                    int myj = j + half;
                    int pke = __shfl_sync(0xffffffffu, pk, myj);
                    bool act = (myj < cnt);
                    float y[8];
                    if (act) {
                        int s   = pke & 0x1FFFF;
                        int bin = ((unsigned)pke) >> 17;
                        uint4 ua = reinterpret_cast<const uint4*>(g_hs)[s * 16 + t];
                        uint4 ut = reinterpret_cast<const uint4*>(g_tab)[bin * 16 + t];
                        float m[8];
#pragma unroll
                        for (int q = 0; q < 4; ++q) {
                            float2 va = __half22float2(reinterpret_cast<const __half2*>(&ua)[q]);
                            float2 vt = __half22float2(reinterpret_cast<const __half2*>(&ut)[q]);
                            m[2 * q]     = va.x + vb[q].x + vt.x;
                            m[2 * q + 1] = va.y + vb[q].y + vt.y;
                        }
                        y[0] = A0.x * m[0] + B0.x;  y[1] = A0.y * m[1] + B0.y;
                        y[2] = A0.z * m[2] + B0.z;  y[3] = A0.w * m[3] + B0.w;
                        y[4] = A1.x * m[4] + B1.x;  y[5] = A1.y * m[5] + B1.y;
                        y[6] = A1.z * m[6] + B1.z;  y[7] = A1.w * m[7] + B1.w;
                    } else {
#pragma unroll
                        for (int i = 0; i < 8; ++i) y[i] = 0.0f;
                    }
                    // partner channels (c+64) live on sub-lane t+8 of same half
                    float p[8];
#pragma unroll
                    for (int i = 0; i < 8; ++i)
                        p[i] = __shfl_down_sync(0xffffffffu, y[i], 8);
                    if (act && t < 8) {
#pragma unroll
                        for (int i = 0; i < 8; ++i)
                            hacc[i] += sig_f(y[i]) * sp_f(p[i]);
                    }
                }
            }
        }
        // combine the two halves: lanes 0..7 += lanes 16..23
        float tot[8];
#pragma unroll
        for (int i = 0; i < 8; ++i) {
            float o = __shfl_down_sync(0xffffffffu, hacc[i], 16);
            tot[i] = hacc[i] + o;
        }
        if (lane < 8) {
            float4 o0 = make_float4(tot[0], tot[1], tot[2], tot[3]);
            float4 o1 = make_float4(tot[4], tot[5], tot[6], tot[7]);
            float* base = g_h + n * NF + lane * 8;
            *reinterpret_cast<float4*>(base)     = o0;
            *reinterpret_cast<float4*>(base + 4) = o1;
#pragma unroll
            for (int i = 0; i < 8; ++i) {
                hsum[i] += tot[i];
                hsq[i]  += tot[i] * tot[i];
            }
        }
    }
    // fused node-BN stats: lane<8 holds channels lane*8+i
    __shared__ float ss[NF], sq[NF];
    if (threadIdx.x < NF) { ss[threadIdx.x] = 0.0f; sq[threadIdx.x] = 0.0f; }
    __syncthreads();
    if (lane < 8) {
#pragma unroll
        for (int i = 0; i < 8; ++i) {
            atomicAdd(&ss[lane * 8 + i], hsum[i]);
            atomicAdd(&sq[lane * 8 + i], hsq[i]);
        }
    }
    __syncthreads();
    if (threadIdx.x < NF) {
        atomicAdd(&g_nsum[threadIdx.x], ss[threadIdx.x]);
        atomicAdd(&g_nsq [threadIdx.x], sq[threadIdx.x]);
    }
}

// --------------- x = softplus(x + BN(h)) ----------------------------------
__global__ __launch_bounds__(256) void k_node_update(const float* __restrict__ gb,
                                                     const float* __restrict__ bb, int l) {
    int i = blockIdx.x * blockDim.x + threadIdx.x;
    const int total = NN * NF;
    for (; i < total; i += gridDim.x * blockDim.x) {
        int c = i & 63;
        float mean = g_nsum[c] * (1.0f / NN);
        float var  = fmaxf(g_nsq[c] * (1.0f / NN) - mean * mean, 0.0f);
        float A = gb[l * NF + c] * rsqrtf(var + BN_EPS);
        float B = bb[l * NF + c] - mean * A;
        float v = g_x[i] + A * g_h[i] + B;
        g_x[i] = sp_f(v);
    }
}

// --------------- readout --------------------------------------------------
__global__ __launch_bounds__(256) void k_pool(const int* __restrict__ gid) {
    const int lane = threadIdx.x & 31;
    int w = (blockIdx.x * blockDim.x + threadIdx.x) >> 5;
    const int nw = (gridDim.x * blockDim.x) >> 5;
    for (int n = w; n < NN; n += nw) {
        int g = __ldg(&gid[n]);
        if (lane < 16) {
            float4 v = reinterpret_cast<const float4*>(g_x + n * NF)[lane];
            atomicAdd(reinterpret_cast<float4*>(g_pool + g * NF + lane * 4), v);
        } else if (lane == 16) {
            atomicAdd(&g_cnt[g], 1.0f);
        }
    }
}
__global__ void k_div(float* __restrict__ out) {
    int i = blockIdx.x * blockDim.x + threadIdx.x;      // 64*256 = 16384
    if (i < NGR * NF)
        out[i] = g_pool[i] / fmaxf(g_cnt[i >> 6], 1.0f);
}

// ---------------- launcher ------------------------------------------------
extern "C" void kernel_launch(void* const* d_in, const int* in_sizes, int n_in,
                              void* d_out, int out_size) {
    const int*   atom_types = (const int*)  d_in[0];
    const float* distances  = (const float*)d_in[1];
    const int*   src        = (const int*)  d_in[2];
    const int*   dst        = (const int*)  d_in[3];
    const int*   gid        = (const int*)  d_in[4];
    const int base = (in_sizes[5] == 1) ? 6 : 5;   // n_graphs may be materialized
    const float* atom_table = (const float*)d_in[base + 0];
    const float* W_embed    = (const float*)d_in[base + 1];
    const float* b_embed    = (const float*)d_in[base + 2];
    const float* W_src      = (const float*)d_in[base + 3];
    const float* b_src      = (const float*)d_in[base + 4];
    const float* W_dst      = (const float*)d_in[base + 5];
    const float* b_dst      = (const float*)d_in[base + 6];
    const float* W_edge     = (const float*)d_in[base + 7];
    const float* b_edge     = (const float*)d_in[base + 8];
    const float* g_msg      = (const float*)d_in[base + 9];
    const float* beta_msg   = (const float*)d_in[base + 10];
    const float* g_bn       = (const float*)d_in[base + 11];
    const float* beta_bn    = (const float*)d_in[base + 12];
    float* out = (float*)d_out;

    k_emb<<<NAT, NF>>>(atom_table, W_embed, b_embed);
    k_gather_x<<<1024, 256>>>(atom_types);

    // one-time CSR by dst (reused for all layers & both passes)
    k_csr_zero<<<128, 256>>>();
    k_csr_hist<<<1024, 256>>>(dst);
    k_scan<<<1, 1024>>>();
    k_csr_scatter<<<1024, 256>>>(src, dst, distances);

    for (int l = 0; l < NL; ++l) {
        k_tab<<<(TAB + 4) / 4, NF2>>>(W_edge, b_edge, l);   // also zeroes edge stats
        k_node_gemm<<<dim3((NN + 127) / 128, 2), 256>>>(W_src, b_src, W_dst, b_dst, l);
        k_edge_stats<<<2048, 256>>>();
        k_finalize<<<1, NF2>>>(g_msg, beta_msg, l);         // also zeroes node stats
        k_edge_apply<<<2048, 256>>>();                      // no atomics + fused stats
        k_node_update<<<1024, 256>>>(g_bn, beta_bn, l);
    }

    k_pool_zero<<<65, 256>>>();
    k_pool<<<512, 256>>>(gid);
    k_div<<<64, 256>>>(out);
}

// round 10
// speedup vs baseline: 1.4968x; 1.2586x over previous
#include <cuda_runtime.h>
#include <cuda_fp16.h>

// ---------------- problem constants (fixed by the dataset) ----------------
#define NN   100000     // nodes
#define NE   1600000    // edges
#define NGR  256        // graphs
#define NF   64         // node feat
#define NF2  128        // 2*NF
#define EFB  40         // rbf bins
#define NL   3          // layers
#define NAT  95         // atom types
#define NAF  200        // atom feat
#define TAB  8192       // e_lin nearest-lookup intervals over [0,8]
#define BN_EPS 1e-5f

// Channel-permuted storage for hs/hd/tab/AB:
//   storage pos p = 8g+r:  r<4 -> orig gate channel 4g+r ; r>=4 -> orig value 64+4g+(r-4)
// So each lane's uint4 (8 halves) = {4 gate ch, 4 partner value ch}.
__device__ __forceinline__ int perm_c(int n) {       // orig -> storage
    return (n < 64) ? (((n >> 2) << 3) | (n & 3))
                    : ((((n & 63) >> 2) << 3) | 4 | (n & 3));
}
__device__ __forceinline__ int orig_c(int p) {       // storage -> orig
    int g = p >> 3, r = p & 7;
    return (r < 4) ? ((g << 2) + r) : (64 + (g << 2) + (r - 4));
}

// ---------------- persistent device scratch (no runtime allocation) -------
__device__ float  g_x   [NN * NF];          // node features (fp32)
__device__ __half g_hs  [NN * NF2];         // x @ W_src + b   (fp16, permuted cols)
__device__ __half g_hd  [NN * NF2];         // x @ W_dst + b   (fp16, permuted cols)
__device__ float  g_h   [NN * NF];          // per-node aggregated messages
__device__ __half g_tab [(TAB + 1) * NF2];  // e_lin(d) nearest table (fp16, permuted)
__device__ float  g_emb [NAT * NF];         // atom_table @ W_embed + b
__device__ int    g_rowptr[NN + 1];         // CSR by dst
__device__ int    g_cursor[NN];             // counts, then scatter cursors
__device__ int    g_csr   [NE];             // packed: src | (bin<<17)
__device__ float  g_esum[NF2];              // storage order
__device__ float  g_esq [NF2];
__device__ float  g_AB  [2 * NF2];          // folded BN (storage order)
__device__ float  g_nsum[NF];
__device__ float  g_nsq [NF];
__device__ float  g_pool[NGR * NF];
__device__ float  g_cnt [NGR];

// ---------------- helpers -------------------------------------------------
__device__ __forceinline__ float tanh_f(float x) {
    float r; asm("tanh.approx.f32 %0, %1;" : "=f"(r) : "f"(x)); return r;
}
__device__ __forceinline__ float ex2_f(float x) {
    float r; asm("ex2.approx.f32 %0, %1;" : "=f"(r) : "f"(x)); return r;
}
__device__ __forceinline__ float lg2_f(float x) {
    float r; asm("lg2.approx.f32 %0, %1;" : "=f"(r) : "f"(x)); return r;
}
__device__ __forceinline__ float sig_f(float x) {    // 1 MUFU
    return fmaf(0.5f, tanh_f(0.5f * x), 0.5f);
}
__device__ __forceinline__ float sp_f(float x) {     // 2 MUFU, overflow-safe
    float e = ex2_f(-fabsf(x) * 1.4426950408889634f);
    return fmaxf(x, 0.0f) + 0.6931471805599453f * lg2_f(1.0f + e);
}
__device__ __forceinline__ void mma16816(float c[4],
                                         unsigned a0, unsigned a1, unsigned a2, unsigned a3,
                                         unsigned b0, unsigned b1) {
    asm volatile(
        "mma.sync.aligned.m16n8k16.row.col.f32.f16.f16.f32 "
        "{%0,%1,%2,%3}, {%4,%5,%6,%7}, {%8,%9}, {%0,%1,%2,%3};\n"
        : "+f"(c[0]), "+f"(c[1]), "+f"(c[2]), "+f"(c[3])
        : "r"(a0), "r"(a1), "r"(a2), "r"(a3), "r"(b0), "r"(b1));
}

// --------------- 0a: fold atom featurizer + embedding into [95,64] --------
__global__ void k_emb(const float* __restrict__ at, const float* __restrict__ W,
                      const float* __restrict__ b) {
    int a = blockIdx.x, c = threadIdx.x;               // 95 blocks x 64 threads
    float acc = b[c];
    for (int k = 0; k < NAF; ++k)
        acc += at[a * NAF + k] * W[k * NF + c];
    g_emb[a * NF + c] = acc;
}

// --------------- 0b: x[n] = emb[type[n]] ----------------------------------
__global__ void k_gather_x(const int* __restrict__ types) {
    int i = blockIdx.x * blockDim.x + threadIdx.x;
    const int total = NN * (NF / 4);
    for (; i < total; i += gridDim.x * blockDim.x) {
        int n = i >> 4, j = i & 15;
        int t = __ldg(&types[n]);
        reinterpret_cast<float4*>(g_x)[i] =
            reinterpret_cast<const float4*>(g_emb)[t * (NF / 4) + j];
    }
}

// --------------- CSR build (one-time, reused for all layers) --------------
__global__ void k_csr_zero() {
    int i = blockIdx.x * blockDim.x + threadIdx.x;
    for (; i < NN; i += gridDim.x * blockDim.x) g_cursor[i] = 0;
}
__global__ void k_csr_hist(const int* __restrict__ dst) {
    int e = blockIdx.x * blockDim.x + threadIdx.x;
    for (; e < NE; e += gridDim.x * blockDim.x)
        atomicAdd(&g_cursor[__ldg(&dst[e])], 1);
}
__global__ void k_scan() {
    __shared__ int s[1024];
    __shared__ int carry;
    const int tid = threadIdx.x;
    if (tid == 0) carry = 0;
    __syncthreads();
    for (int base = 0; base < NN; base += 1024) {
        int i = base + tid;
        int v = (i < NN) ? g_cursor[i] : 0;
        s[tid] = v;
        __syncthreads();
        for (int off = 1; off < 1024; off <<= 1) {
            int t = (tid >= off) ? s[tid - off] : 0;
            __syncthreads();
            s[tid] += t;
            __syncthreads();
        }
        int excl = carry + s[tid] - v;
        if (i < NN) { g_rowptr[i] = excl; g_cursor[i] = excl; }
        __syncthreads();
        if (tid == 0) carry += s[1023];
        __syncthreads();
    }
    if (tid == 0) g_rowptr[NN] = carry;    // == NE
}
__global__ void k_csr_scatter(const int* __restrict__ src, const int* __restrict__ dst,
                              const float* __restrict__ dist) {
    int e = blockIdx.x * blockDim.x + threadIdx.x;
    for (; e < NE; e += gridDim.x * blockDim.x) {
        int d = __ldg(&dst[e]);
        int pos = atomicAdd(&g_cursor[d], 1);
        int bin = min(__float2int_rn(__ldg(&dist[e]) * (TAB / 8.0f)), TAB);
        g_csr[pos] = __ldg(&src[e]) | (bin << 17);
    }
}

// --------------- per-layer: build permuted e_lin(d) table (fp16) ----------
__global__ void k_tab(const float* __restrict__ We, const float* __restrict__ be, int l) {
    __shared__ float phi[4][EFB];
    const int p  = threadIdx.x;                         // storage position
    const int oc = orig_c(p);                           // original channel
    const int r0 = blockIdx.x * 4;
    if (p < EFB) {
        float ctr = p * (8.0f / 39.0f);                 // linspace(0,8,40)
#pragma unroll
        for (int r = 0; r < 4; ++r) {
            float x = (r0 + r) * (8.0f / TAB) - ctr;
            phi[r][p] = expf(-4.875f * x * x);          // gamma = 39/8
        }
    }
    __syncthreads();
    const float* W = We + l * EFB * NF2;
    const float bb = be[l * NF2 + oc];
#pragma unroll
    for (int r = 0; r < 4; ++r) {
        if (r0 + r > TAB) break;
        float acc = bb;
#pragma unroll
        for (int k = 0; k < EFB; ++k)
            acc += phi[r][k] * W[k * NF2 + oc];
        g_tab[(r0 + r) * NF2 + p] = __float2half_rn(acc);
    }
    if (blockIdx.x == 0) { g_esum[p] = 0.0f; g_esq[p] = 0.0f; }  // fused zeroing
}

__global__ void k_pool_zero() {
    int i = blockIdx.x * blockDim.x + threadIdx.x;      // 65*256 = 16640
    if (i < NGR * NF) g_pool[i] = 0.0f;
    else if (i < NGR * NF + NGR) g_cnt[i - NGR * NF] = 0.0f;
}

// --------------- node GEMM via tensor cores (permuted output cols) --------
__global__ __launch_bounds__(256) void k_node_gemm(
    const float* __restrict__ Wsrc, const float* __restrict__ bsrc,
    const float* __restrict__ Wdst, const float* __restrict__ bdst, int l) {
    const float* W = (blockIdx.y == 0 ? Wsrc : Wdst) + l * NF * NF2;
    const float* b = (blockIdx.y == 0 ? bsrc : bdst) + l * NF2;
    __half*      H = (blockIdx.y == 0 ? g_hs : g_hd);

    __shared__ __half xs[128 * 72];
    __shared__ __half wt[128 * 72];

    const int tid = threadIdx.x;
    const int nb = blockIdx.x * 128;

#pragma unroll
    for (int i = 0; i < 32; ++i) {                      // W [64][128] -> wt[n][k]
        int idx = i * 256 + tid;
        int k = idx >> 7, n = idx & 127;
        wt[n * 72 + k] = __float2half_rn(W[idx]);
    }
#pragma unroll
    for (int i = 0; i < 16; ++i) {                      // x rows -> xs
        int idx = i * 256 + tid;
        int row = idx >> 5, cp = idx & 31;
        int gr = nb + row; if (gr >= NN) gr = NN - 1;
        float2 v = *reinterpret_cast<const float2*>(g_x + gr * NF + cp * 2);
        *reinterpret_cast<__half2*>(&xs[row * 72 + cp * 2]) = __floats2half2_rn(v.x, v.y);
    }
    __syncthreads();

    const int w = tid >> 5, lane = tid & 31;
    const int m0 = (w & 3) * 32, n0 = (w >> 2) * 64;
    const int lr = lane >> 2, lc = (lane & 3) * 2;

    float c[2][8][4];
#pragma unroll
    for (int mt = 0; mt < 2; ++mt)
#pragma unroll
        for (int nt = 0; nt < 8; ++nt)
            c[mt][nt][0] = c[mt][nt][1] = c[mt][nt][2] = c[mt][nt][3] = 0.0f;

#pragma unroll
    for (int ks = 0; ks < 4; ++ks) {
        const int kk = ks * 16 + lc;
        unsigned bf[8][2];
#pragma unroll
        for (int nt = 0; nt < 8; ++nt) {
            int n = n0 + nt * 8 + lr;
            bf[nt][0] = *reinterpret_cast<unsigned*>(&wt[n * 72 + kk]);
            bf[nt][1] = *reinterpret_cast<unsigned*>(&wt[n * 72 + kk + 8]);
        }
#pragma unroll
        for (int mt = 0; mt < 2; ++mt) {
            int r = m0 + mt * 16 + lr;
            unsigned a0 = *reinterpret_cast<unsigned*>(&xs[r * 72 + kk]);
            unsigned a1 = *reinterpret_cast<unsigned*>(&xs[(r + 8) * 72 + kk]);
            unsigned a2 = *reinterpret_cast<unsigned*>(&xs[r * 72 + kk + 8]);
            unsigned a3 = *reinterpret_cast<unsigned*>(&xs[(r + 8) * 72 + kk + 8]);
#pragma unroll
            for (int nt = 0; nt < 8; ++nt)
                mma16816(c[mt][nt], a0, a1, a2, a3, bf[nt][0], bf[nt][1]);
        }
    }

#pragma unroll
    for (int nt = 0; nt < 8; ++nt) {
        int n = n0 + nt * 8 + lc;                       // original column (even)
        int pos = perm_c(n);                            // permuted (pair-preserving)
        float2 bv = *reinterpret_cast<const float2*>(b + n);
#pragma unroll
        for (int mt = 0; mt < 2; ++mt) {
            int r = nb + m0 + mt * 16 + lr;
            __half2 h01 = __floats2half2_rn(c[mt][nt][0] + bv.x, c[mt][nt][1] + bv.y);
            __half2 h23 = __floats2half2_rn(c[mt][nt][2] + bv.x, c[mt][nt][3] + bv.y);
            if (r < NN)     *reinterpret_cast<__half2*>(H + r * NF2 + pos) = h01;
            if (r + 8 < NN) *reinterpret_cast<__half2*>(H + (r + 8) * NF2 + pos) = h23;
        }
    }
}

// --------------- pass A: CSR-ordered per-channel sum/sumsq of m -----------
// warp per node; hd loaded once; halves process 2 edges/step; sub-lane t: 8 ch
__global__ __launch_bounds__(256) void k_edge_stats() {
    const int lane = threadIdx.x & 31;
    const int half = lane >> 4;
    const int t    = lane & 15;
    int       wid  = (blockIdx.x * blockDim.x + threadIdx.x) >> 5;
    const int nw   = (gridDim.x * blockDim.x) >> 5;
    float2 s2[4], q2[4];
#pragma unroll
    for (int j = 0; j < 4; ++j) { s2[j] = make_float2(0, 0); q2[j] = make_float2(0, 0); }

    for (int n = wid; n < NN; n += nw) {
        const int e0 = __ldg(&g_rowptr[n]);
        const int e1 = __ldg(&g_rowptr[n + 1]);
        if (e0 == e1) continue;
        uint4 ub = reinterpret_cast<const uint4*>(g_hd)[n * 16 + t];
        float2 vb[4];
#pragma unroll
        for (int j = 0; j < 4; ++j)
            vb[j] = __half22float2(reinterpret_cast<const __half2*>(&ub)[j]);

        for (int es = e0; es < e1; es += 32) {
            int pk = (es + lane < e1) ? g_csr[es + lane] : 0;   // coalesced prefetch
            const int cnt = min(32, e1 - es);
            for (int j = 0; j < cnt; j += 2) {
                int myj = j + half;
                int pke = __shfl_sync(0xffffffffu, pk, myj);
                if (myj < cnt) {
                    int s   = pke & 0x1FFFF;
                    int bin = ((unsigned)pke) >> 17;
                    uint4 ua = reinterpret_cast<const uint4*>(g_hs)[s * 16 + t];
                    uint4 ut = reinterpret_cast<const uint4*>(g_tab)[bin * 16 + t];
#pragma unroll
                    for (int q = 0; q < 4; ++q) {
                        float2 va = __half22float2(reinterpret_cast<const __half2*>(&ua)[q]);
                        float2 vt = __half22float2(reinterpret_cast<const __half2*>(&ut)[q]);
                        float mx = va.x + vb[q].x + vt.x;
                        float my = va.y + vb[q].y + vt.y;
                        s2[q].x += mx;      s2[q].y += my;
                        q2[q].x += mx * mx; q2[q].y += my * my;
                    }
                }
            }
        }
    }
    __shared__ float ss[NF2], sq[NF2];
    if (threadIdx.x < NF2) { ss[threadIdx.x] = 0.0f; sq[threadIdx.x] = 0.0f; }
    __syncthreads();
#pragma unroll
    for (int j = 0; j < 4; ++j) {
        atomicAdd(&ss[t * 8 + 2 * j],     s2[j].x);
        atomicAdd(&ss[t * 8 + 2 * j + 1], s2[j].y);
        atomicAdd(&sq[t * 8 + 2 * j],     q2[j].x);
        atomicAdd(&sq[t * 8 + 2 * j + 1], q2[j].y);
    }
    __syncthreads();
    if (threadIdx.x < NF2) {
        atomicAdd(&g_esum[threadIdx.x], ss[threadIdx.x]);
        atomicAdd(&g_esq [threadIdx.x], sq[threadIdx.x]);
    }
}

// --------------- fold BN into y = A*m + B (storage order) -----------------
__global__ void k_finalize(const float* __restrict__ gm, const float* __restrict__ bm, int l) {
    int p = threadIdx.x;                                // 128, storage pos
    int oc = orig_c(p);
    float mean = g_esum[p] * (1.0f / NE);
    float var  = fmaxf(g_esq[p] * (1.0f / NE) - mean * mean, 0.0f);
    float A = gm[l * NF2 + oc] * rsqrtf(var + BN_EPS);
    g_AB[p]       = A;
    g_AB[NF2 + p] = bm[l * NF2 + oc] - mean * A;
    if (p < NF) { g_nsum[p] = 0.0f; g_nsq[p] = 0.0f; }  // fused zeroing
}

// --------------- pass B: CSR gather, dense gate, per-node reg accumulate --
// Permuted layout: each lane's uint4 holds 4 gate + 4 partner value channels,
// so ALL 32 lanes run the MUFU gating (sig=tanh 1 MUFU, sp=2 MUFU). No atomics.
__global__ __launch_bounds__(256) void k_edge_apply() {
    const int lane = threadIdx.x & 31;
    const int half = lane >> 4;
    const int t    = lane & 15;
    int       wid  = (blockIdx.x * blockDim.x + threadIdx.x) >> 5;
    const int nw   = (gridDim.x * blockDim.x) >> 5;

    const float4 A0 = reinterpret_cast<const float4*>(g_AB)[t * 2];      // gates
    const float4 A1 = reinterpret_cast<const float4*>(g_AB)[t * 2 + 1];  // values
    const float4 B0 = reinterpret_cast<const float4*>(g_AB + NF2)[t * 2];
    const float4 B1 = reinterpret_cast<const float4*>(g_AB + NF2)[t * 2 + 1];

    float hsum[4], hsq[4];
#pragma unroll
    for (int i = 0; i < 4; ++i) { hsum[i] = 0.0f; hsq[i] = 0.0f; }

    for (int n = wid; n < NN; n += nw) {
        const int e0 = __ldg(&g_rowptr[n]);
        const int e1 = __ldg(&g_rowptr[n + 1]);

        float hacc[4];
#pragma unroll
        for (int i = 0; i < 4; ++i) hacc[i] = 0.0f;

        if (e0 != e1) {
            uint4 ub = reinterpret_cast<const uint4*>(g_hd)[n * 16 + t];
            float2 vb[4];
#pragma unroll
            for (int j = 0; j < 4; ++j)
                vb[j] = __half22float2(reinterpret_cast<const __half2*>(&ub)[j]);

            for (int es = e0; es < e1; es += 32) {
                int pk = (es + lane < e1) ? g_csr[es + lane] : 0;
                const int cnt = min(32, e1 - es);
                for (int j = 0; j < cnt; j += 2) {
                    int myj = j + half;
                    int pke = __shfl_sync(0xffffffffu, pk, myj);
                    if (myj < cnt) {
                        int s   = pke & 0x1FFFF;
                        int bin = ((unsigned)pke) >> 17;
                        uint4 ua = reinterpret_cast<const uint4*>(g_hs)[s * 16 + t];
                        uint4 ut = reinterpret_cast<const uint4*>(g_tab)[bin * 16 + t];
                        float m[8];
#pragma unroll
                        for (int q = 0; q < 4; ++q) {
                            float2 va = __half22float2(reinterpret_cast<const __half2*>(&ua)[q]);
                            float2 vt = __half22float2(reinterpret_cast<const __half2*>(&ut)[q]);
                            m[2 * q]     = va.x + vb[q].x + vt.x;
                            m[2 * q + 1] = va.y + vb[q].y + vt.y;
                        }
                        // gates: m[0..3] (storage 8t..8t+3), values: m[4..7]
                        float yg0 = A0.x * m[0] + B0.x;
                        float yg1 = A0.y * m[1] + B0.y;
                        float yg2 = A0.z * m[2] + B0.z;
                        float yg3 = A0.w * m[3] + B0.w;
                        float yv0 = A1.x * m[4] + B1.x;
                        float yv1 = A1.y * m[5] + B1.y;
                        float yv2 = A1.z * m[6] + B1.z;
                        float yv3 = A1.w * m[7] + B1.w;
                        hacc[0] += sig_f(yg0) * sp_f(yv0);
                        hacc[1] += sig_f(yg1) * sp_f(yv1);
                        hacc[2] += sig_f(yg2) * sp_f(yv2);
                        hacc[3] += sig_f(yg3) * sp_f(yv3);
                    }
                }
            }
        }
        // combine halves: lane t (<16) += lane t+16
        float tot[4];
#pragma unroll
        for (int i = 0; i < 4; ++i) {
            float o = __shfl_down_sync(0xffffffffu, hacc[i], 16);
            tot[i] = hacc[i] + o;
        }
        if (lane < 16) {
            // output channels 4t..4t+3 (original order)
            *reinterpret_cast<float4*>(g_h + n * NF + lane * 4) =
                make_float4(tot[0], tot[1], tot[2], tot[3]);
#pragma unroll
            for (int i = 0; i < 4; ++i) {
                hsum[i] += tot[i];
                hsq[i]  += tot[i] * tot[i];
            }
        }
    }
    // fused node-BN stats: lane<16 holds channels 4t+i
    __shared__ float ss[NF], sq[NF];
    if (threadIdx.x < NF) { ss[threadIdx.x] = 0.0f; sq[threadIdx.x] = 0.0f; }
    __syncthreads();
    if (lane < 16) {
#pragma unroll
        for (int i = 0; i < 4; ++i) {
            atomicAdd(&ss[t * 4 + i], hsum[i]);
            atomicAdd(&sq[t * 4 + i], hsq[i]);
        }
    }
    __syncthreads();
    if (threadIdx.x < NF) {
        atomicAdd(&g_nsum[threadIdx.x], ss[threadIdx.x]);
        atomicAdd(&g_nsq [threadIdx.x], sq[threadIdx.x]);
    }
}

// --------------- x = softplus(x + BN(h)) ----------------------------------
__global__ __launch_bounds__(256) void k_node_update(const float* __restrict__ gb,
                                                     const float* __restrict__ bb, int l) {
    int i = blockIdx.x * blockDim.x + threadIdx.x;
    const int total = NN * NF;
    for (; i < total; i += gridDim.x * blockDim.x) {
        int c = i & 63;
        float mean = g_nsum[c] * (1.0f / NN);
        float var  = fmaxf(g_nsq[c] * (1.0f / NN) - mean * mean, 0.0f);
        float A = gb[l * NF + c] * rsqrtf(var + BN_EPS);
        float B = bb[l * NF + c] - mean * A;
        float v = g_x[i] + A * g_h[i] + B;
        g_x[i] = sp_f(v);
    }
}

// --------------- readout --------------------------------------------------
__global__ __launch_bounds__(256) void k_pool(const int* __restrict__ gid) {
    const int lane = threadIdx.x & 31;
    int w = (blockIdx.x * blockDim.x + threadIdx.x) >> 5;
    const int nw = (gridDim.x * blockDim.x) >> 5;
    for (int n = w; n < NN; n += nw) {
        int g = __ldg(&gid[n]);
        if (lane < 16) {
            float4 v = reinterpret_cast<const float4*>(g_x + n * NF)[lane];
            atomicAdd(reinterpret_cast<float4*>(g_pool + g * NF + lane * 4), v);
        } else if (lane == 16) {
            atomicAdd(&g_cnt[g], 1.0f);
        }
    }
}
__global__ void k_div(float* __restrict__ out) {
    int i = blockIdx.x * blockDim.x + threadIdx.x;      // 64*256 = 16384
    if (i < NGR * NF)
        out[i] = g_pool[i] / fmaxf(g_cnt[i >> 6], 1.0f);
}

// ---------------- launcher ------------------------------------------------
extern "C" void kernel_launch(void* const* d_in, const int* in_sizes, int n_in,
                              void* d_out, int out_size) {
    const int*   atom_types = (const int*)  d_in[0];
    const float* distances  = (const float*)d_in[1];
    const int*   src        = (const int*)  d_in[2];
    const int*   dst        = (const int*)  d_in[3];
    const int*   gid        = (const int*)  d_in[4];
    const int base = (in_sizes[5] == 1) ? 6 : 5;   // n_graphs may be materialized
    const float* atom_table = (const float*)d_in[base + 0];
    const float* W_embed    = (const float*)d_in[base + 1];
    const float* b_embed    = (const float*)d_in[base + 2];
    const float* W_src      = (const float*)d_in[base + 3];
    const float* b_src      = (const float*)d_in[base + 4];
    const float* W_dst      = (const float*)d_in[base + 5];
    const float* b_dst      = (const float*)d_in[base + 6];
    const float* W_edge     = (const float*)d_in[base + 7];
    const float* b_edge     = (const float*)d_in[base + 8];
    const float* g_msg      = (const float*)d_in[base + 9];
    const float* beta_msg   = (const float*)d_in[base + 10];
    const float* g_bn       = (const float*)d_in[base + 11];
    const float* beta_bn    = (const float*)d_in[base + 12];
    float* out = (float*)d_out;

    k_emb<<<NAT, NF>>>(atom_table, W_embed, b_embed);
    k_gather_x<<<1024, 256>>>(atom_types);

    // one-time CSR by dst (reused for all layers & both passes)
    k_csr_zero<<<128, 256>>>();
    k_csr_hist<<<1024, 256>>>(dst);
    k_scan<<<1, 1024>>>();
    k_csr_scatter<<<1024, 256>>>(src, dst, distances);

    for (int l = 0; l < NL; ++l) {
        k_tab<<<(TAB + 4) / 4, NF2>>>(W_edge, b_edge, l);   // also zeroes edge stats
        k_node_gemm<<<dim3((NN + 127) / 128, 2), 256>>>(W_src, b_src, W_dst, b_dst, l);
        k_edge_stats<<<2048, 256>>>();
        k_finalize<<<1, NF2>>>(g_msg, beta_msg, l);         // also zeroes node stats
        k_edge_apply<<<2048, 256>>>();                      // dense MUFU, no atomics
        k_node_update<<<1024, 256>>>(g_bn, beta_bn, l);
    }

    k_pool_zero<<<65, 256>>>();
    k_pool<<<512, 256>>>(gid);
    k_div<<<64, 256>>>(out);
}

// round 11
// speedup vs baseline: 1.6661x; 1.1131x over previous
#include <cuda_runtime.h>
#include <cuda_fp16.h>

// ---------------- problem constants (fixed by the dataset) ----------------
#define NN   100000     // nodes
#define NE   1600000    // edges
#define NGR  256        // graphs
#define NF   64         // node feat
#define NF2  128        // 2*NF
#define EFB  40         // rbf bins
#define NL   3          // layers
#define NAT  95         // atom types
#define NAF  200        // atom feat
#define TAB  8192       // e_lin nearest-lookup intervals over [0,8]
#define BN_EPS 1e-5f
#define NCHUNK ((NN + 1023) / 1024)   // 98 scan chunks

// Channel-permuted storage for hs/hd/tab/AB:
//   storage pos p = 8g+r:  r<4 -> orig gate channel 4g+r ; r>=4 -> orig value 64+4g+(r-4)
__device__ __forceinline__ int perm_c(int n) {       // orig -> storage
    return (n < 64) ? (((n >> 2) << 3) | (n & 3))
                    : ((((n & 63) >> 2) << 3) | 4 | (n & 3));
}
__device__ __forceinline__ int orig_c(int p) {       // storage -> orig
    int g = p >> 3, r = p & 7;
    return (r < 4) ? ((g << 2) + r) : (64 + (g << 2) + (r - 4));
}

// ---------------- persistent device scratch (no runtime allocation) -------
__device__ float  g_x   [NN * NF];
__device__ __half g_hs  [NN * NF2];         // permuted cols
__device__ __half g_hd  [NN * NF2];         // permuted cols
__device__ float  g_h   [NN * NF];
__device__ __half g_tab [(TAB + 1) * NF2];  // permuted cols
__device__ float  g_emb [NAT * NF];
__device__ int    g_rowptr[NN + 1];
__device__ int    g_cursor[NN];
__device__ int    g_blk [128];              // scan block sums
__device__ int    g_csr [NE];               // packed: src | (bin<<17)
__device__ float  g_esum[NF2];
__device__ float  g_esq [NF2];
__device__ float  g_AB  [2 * NF2];
__device__ float  g_nsum[NF];
__device__ float  g_nsq [NF];
__device__ float  g_pool[NGR * NF];
__device__ float  g_cnt [NGR];

// ---------------- helpers -------------------------------------------------
__device__ __forceinline__ float tanh_f(float x) {
    float r; asm("tanh.approx.f32 %0, %1;" : "=f"(r) : "f"(x)); return r;
}
__device__ __forceinline__ float ex2_f(float x) {
    float r; asm("ex2.approx.f32 %0, %1;" : "=f"(r) : "f"(x)); return r;
}
__device__ __forceinline__ float lg2_f(float x) {
    float r; asm("lg2.approx.f32 %0, %1;" : "=f"(r) : "f"(x)); return r;
}
__device__ __forceinline__ float sig_f(float x) {    // 1 MUFU
    return fmaf(0.5f, tanh_f(0.5f * x), 0.5f);
}
__device__ __forceinline__ float sp_f(float x) {     // 2 MUFU, overflow-safe
    float e = ex2_f(-fabsf(x) * 1.4426950408889634f);
    return fmaxf(x, 0.0f) + 0.6931471805599453f * lg2_f(1.0f + e);
}
__device__ __forceinline__ void mma16816(float c[4],
                                         unsigned a0, unsigned a1, unsigned a2, unsigned a3,
                                         unsigned b0, unsigned b1) {
    asm volatile(
        "mma.sync.aligned.m16n8k16.row.col.f32.f16.f16.f32 "
        "{%0,%1,%2,%3}, {%4,%5,%6,%7}, {%8,%9}, {%0,%1,%2,%3};\n"
        : "+f"(c[0]), "+f"(c[1]), "+f"(c[2]), "+f"(c[3])
        : "r"(a0), "r"(a1), "r"(a2), "r"(a3), "r"(b0), "r"(b1));
}

// --------------- 0a: fold atom featurizer + embedding into [95,64] --------
__global__ void k_emb(const float* __restrict__ at, const float* __restrict__ W,
                      const float* __restrict__ b) {
    int a = blockIdx.x, c = threadIdx.x;
    float acc = b[c];
    for (int k = 0; k < NAF; ++k)
        acc += at[a * NAF + k] * W[k * NF + c];
    g_emb[a * NF + c] = acc;
}

// --------------- 0b: x[n] = emb[type[n]]  (+ fused cursor zeroing) --------
__global__ void k_gather_x(const int* __restrict__ types) {
    int i0 = blockIdx.x * blockDim.x + threadIdx.x;
    for (int i = i0; i < NN; i += gridDim.x * blockDim.x) g_cursor[i] = 0;
    const int total = NN * (NF / 4);
    for (int i = i0; i < total; i += gridDim.x * blockDim.x) {
        int n = i >> 4, j = i & 15;
        int t = __ldg(&types[n]);
        reinterpret_cast<float4*>(g_x)[i] =
            reinterpret_cast<const float4*>(g_emb)[t * (NF / 4) + j];
    }
}

// --------------- CSR build (one-time) -------------------------------------
__global__ void k_csr_hist(const int* __restrict__ dst) {
    int e = blockIdx.x * blockDim.x + threadIdx.x;
    for (; e < NE; e += gridDim.x * blockDim.x)
        atomicAdd(&g_cursor[__ldg(&dst[e])], 1);
}
// phase 1: per-1024-chunk exclusive scan (shuffle-based) + block totals
__global__ void k_scan1() {
    __shared__ int wsum[32];
    const int tid = threadIdx.x;
    const int i = blockIdx.x * 1024 + tid;
    int v = (i < NN) ? g_cursor[i] : 0;
    int x = v;
#pragma unroll
    for (int off = 1; off < 32; off <<= 1) {
        int y = __shfl_up_sync(0xffffffffu, x, off);
        if ((tid & 31) >= off) x += y;
    }
    if ((tid & 31) == 31) wsum[tid >> 5] = x;
    __syncthreads();
    if (tid < 32) {
        int w = wsum[tid];
#pragma unroll
        for (int off = 1; off < 32; off <<= 1) {
            int y = __shfl_up_sync(0xffffffffu, w, off);
            if (tid >= off) w += y;
        }
        wsum[tid] = w;                       // inclusive over warp sums
    }
    __syncthreads();
    int warpoff = (tid >= 32) ? wsum[(tid >> 5) - 1] : 0;
    int excl = warpoff + x - v;
    if (i < NN) g_rowptr[i] = excl;          // exclusive within chunk
    if (tid == 1023) g_blk[blockIdx.x] = warpoff + x;   // chunk total
}
// phase 2: scan the 98 chunk totals (single block)
__global__ void k_scan2() {
    __shared__ int s[128];
    const int tid = threadIdx.x;             // 128
    int v = (tid < NCHUNK) ? g_blk[tid] : 0;
    s[tid] = v;
    __syncthreads();
    for (int off = 1; off < 128; off <<= 1) {
        int t = (tid >= off) ? s[tid - off] : 0;
        __syncthreads();
        s[tid] += t;
        __syncthreads();
    }
    if (tid < NCHUNK) g_blk[tid] = s[tid] - v;   // exclusive chunk offsets
}
// phase 3: add chunk offsets, init cursors
__global__ void k_scan3() {
    int i = blockIdx.x * blockDim.x + threadIdx.x;
    for (; i < NN; i += gridDim.x * blockDim.x) {
        int r = g_rowptr[i] + g_blk[i >> 10];
        g_rowptr[i] = r;
        g_cursor[i] = r;
    }
    if (blockIdx.x == 0 && threadIdx.x == 0) g_rowptr[NN] = NE;
}
__global__ void k_csr_scatter(const int* __restrict__ src, const int* __restrict__ dst,
                              const float* __restrict__ dist) {
    int e = blockIdx.x * blockDim.x + threadIdx.x;
    for (; e < NE; e += gridDim.x * blockDim.x) {
        int d = __ldg(&dst[e]);
        int pos = atomicAdd(&g_cursor[d], 1);
        int bin = min(__float2int_rn(__ldg(&dist[e]) * (TAB / 8.0f)), TAB);
        g_csr[pos] = __ldg(&src[e]) | (bin << 17);
    }
}

// --------------- per-layer: build permuted e_lin(d) table (fp16) ----------
__global__ void k_tab(const float* __restrict__ We, const float* __restrict__ be, int l) {
    __shared__ float phi[4][EFB];
    const int p  = threadIdx.x;                         // storage position
    const int oc = orig_c(p);
    const int r0 = blockIdx.x * 4;
    if (p < EFB) {
        float ctr = p * (8.0f / 39.0f);
#pragma unroll
        for (int r = 0; r < 4; ++r) {
            float x = (r0 + r) * (8.0f / TAB) - ctr;
            phi[r][p] = expf(-4.875f * x * x);
        }
    }
    __syncthreads();
    const float* W = We + l * EFB * NF2;
    const float bb = be[l * NF2 + oc];
#pragma unroll
    for (int r = 0; r < 4; ++r) {
        if (r0 + r > TAB) break;
        float acc = bb;
#pragma unroll
        for (int k = 0; k < EFB; ++k)
            acc += phi[r][k] * W[k * NF2 + oc];
        g_tab[(r0 + r) * NF2 + p] = __float2half_rn(acc);
    }
    if (blockIdx.x == 0) { g_esum[p] = 0.0f; g_esq[p] = 0.0f; }
}

// --------------- node GEMM via tensor cores (permuted output cols) --------
__global__ __launch_bounds__(256) void k_node_gemm(
    const float* __restrict__ Wsrc, const float* __restrict__ bsrc,
    const float* __restrict__ Wdst, const float* __restrict__ bdst, int l) {
    const float* W = (blockIdx.y == 0 ? Wsrc : Wdst) + l * NF * NF2;
    const float* b = (blockIdx.y == 0 ? bsrc : bdst) + l * NF2;
    __half*      H = (blockIdx.y == 0 ? g_hs : g_hd);

    __shared__ __half xs[128 * 72];
    __shared__ __half wt[128 * 72];

    const int tid = threadIdx.x;
    const int nb = blockIdx.x * 128;

#pragma unroll
    for (int i = 0; i < 32; ++i) {
        int idx = i * 256 + tid;
        int k = idx >> 7, n = idx & 127;
        wt[n * 72 + k] = __float2half_rn(W[idx]);
    }
#pragma unroll
    for (int i = 0; i < 16; ++i) {
        int idx = i * 256 + tid;
        int row = idx >> 5, cp = idx & 31;
        int gr = nb + row; if (gr >= NN) gr = NN - 1;
        float2 v = *reinterpret_cast<const float2*>(g_x + gr * NF + cp * 2);
        *reinterpret_cast<__half2*>(&xs[row * 72 + cp * 2]) = __floats2half2_rn(v.x, v.y);
    }
    __syncthreads();

    const int w = tid >> 5, lane = tid & 31;
    const int m0 = (w & 3) * 32, n0 = (w >> 2) * 64;
    const int lr = lane >> 2, lc = (lane & 3) * 2;

    float c[2][8][4];
#pragma unroll
    for (int mt = 0; mt < 2; ++mt)
#pragma unroll
        for (int nt = 0; nt < 8; ++nt)
            c[mt][nt][0] = c[mt][nt][1] = c[mt][nt][2] = c[mt][nt][3] = 0.0f;

#pragma unroll
    for (int ks = 0; ks < 4; ++ks) {
        const int kk = ks * 16 + lc;
        unsigned bf[8][2];
#pragma unroll
        for (int nt = 0; nt < 8; ++nt) {
            int n = n0 + nt * 8 + lr;
            bf[nt][0] = *reinterpret_cast<unsigned*>(&wt[n * 72 + kk]);
            bf[nt][1] = *reinterpret_cast<unsigned*>(&wt[n * 72 + kk + 8]);
        }
#pragma unroll
        for (int mt = 0; mt < 2; ++mt) {
            int r = m0 + mt * 16 + lr;
            unsigned a0 = *reinterpret_cast<unsigned*>(&xs[r * 72 + kk]);
            unsigned a1 = *reinterpret_cast<unsigned*>(&xs[(r + 8) * 72 + kk]);
            unsigned a2 = *reinterpret_cast<unsigned*>(&xs[r * 72 + kk + 8]);
            unsigned a3 = *reinterpret_cast<unsigned*>(&xs[(r + 8) * 72 + kk + 8]);
#pragma unroll
            for (int nt = 0; nt < 8; ++nt)
                mma16816(c[mt][nt], a0, a1, a2, a3, bf[nt][0], bf[nt][1]);
        }
    }

#pragma unroll
    for (int nt = 0; nt < 8; ++nt) {
        int n = n0 + nt * 8 + lc;
        int pos = perm_c(n);
        float2 bv = *reinterpret_cast<const float2*>(b + n);
#pragma unroll
        for (int mt = 0; mt < 2; ++mt) {
            int r = nb + m0 + mt * 16 + lr;
            __half2 h01 = __floats2half2_rn(c[mt][nt][0] + bv.x, c[mt][nt][1] + bv.y);
            __half2 h23 = __floats2half2_rn(c[mt][nt][2] + bv.x, c[mt][nt][3] + bv.y);
            if (r < NN)     *reinterpret_cast<__half2*>(H + r * NF2 + pos) = h01;
            if (r + 8 < NN) *reinterpret_cast<__half2*>(H + (r + 8) * NF2 + pos) = h23;
        }
    }
}

// --------------- pass A: CSR stats, 2-edge unrolled (MLP=4) ---------------
__global__ __launch_bounds__(256) void k_edge_stats() {
    const int lane = threadIdx.x & 31;
    const int half = lane >> 4;
    const int t    = lane & 15;
    int       wid  = (blockIdx.x * blockDim.x + threadIdx.x) >> 5;
    const int nw   = (gridDim.x * blockDim.x) >> 5;
    float2 s2[4], q2[4];
#pragma unroll
    for (int j = 0; j < 4; ++j) { s2[j] = make_float2(0, 0); q2[j] = make_float2(0, 0); }

    for (int n = wid; n < NN; n += nw) {
        const int e0 = __ldg(&g_rowptr[n]);
        const int e1 = __ldg(&g_rowptr[n + 1]);
        if (e0 == e1) continue;
        uint4 ub = reinterpret_cast<const uint4*>(g_hd)[n * 16 + t];
        float2 vb[4];
#pragma unroll
        for (int j = 0; j < 4; ++j)
            vb[j] = __half22float2(reinterpret_cast<const __half2*>(&ub)[j]);

        for (int es = e0; es < e1; es += 32) {
            int pk = (es + lane < e1) ? g_csr[es + lane] : 0;
            const int cnt = min(32, e1 - es);
            for (int j = 0; j < cnt; j += 4) {
                int j0 = j + half, j1 = j + 2 + half;
                int pk0 = __shfl_sync(0xffffffffu, pk, j0 & 31);
                int pk1 = __shfl_sync(0xffffffffu, pk, j1 & 31);
                bool a0 = (j0 < cnt), a1 = (j1 < cnt);
                uint4 ua0, ut0, ua1, ut1;
                if (a0) {
                    ua0 = reinterpret_cast<const uint4*>(g_hs)[(pk0 & 0x1FFFF) * 16 + t];
                    ut0 = reinterpret_cast<const uint4*>(g_tab)[(((unsigned)pk0) >> 17) * 16 + t];
                }
                if (a1) {
                    ua1 = reinterpret_cast<const uint4*>(g_hs)[(pk1 & 0x1FFFF) * 16 + t];
                    ut1 = reinterpret_cast<const uint4*>(g_tab)[(((unsigned)pk1) >> 17) * 16 + t];
                }
                if (a0) {
#pragma unroll
                    for (int q = 0; q < 4; ++q) {
                        float2 va = __half22float2(reinterpret_cast<const __half2*>(&ua0)[q]);
                        float2 vt = __half22float2(reinterpret_cast<const __half2*>(&ut0)[q]);
                        float mx = va.x + vb[q].x + vt.x;
                        float my = va.y + vb[q].y + vt.y;
                        s2[q].x += mx;      s2[q].y += my;
                        q2[q].x += mx * mx; q2[q].y += my * my;
                    }
                }
                if (a1) {
#pragma unroll
                    for (int q = 0; q < 4; ++q) {
                        float2 va = __half22float2(reinterpret_cast<const __half2*>(&ua1)[q]);
                        float2 vt = __half22float2(reinterpret_cast<const __half2*>(&ut1)[q]);
                        float mx = va.x + vb[q].x + vt.x;
                        float my = va.y + vb[q].y + vt.y;
                        s2[q].x += mx;      s2[q].y += my;
                        q2[q].x += mx * mx; q2[q].y += my * my;
                    }
                }
            }
        }
    }
    __shared__ float ss[NF2], sq[NF2];
    if (threadIdx.x < NF2) { ss[threadIdx.x] = 0.0f; sq[threadIdx.x] = 0.0f; }
    __syncthreads();
#pragma unroll
    for (int j = 0; j < 4; ++j) {
        atomicAdd(&ss[t * 8 + 2 * j],     s2[j].x);
        atomicAdd(&ss[t * 8 + 2 * j + 1], s2[j].y);
        atomicAdd(&sq[t * 8 + 2 * j],     q2[j].x);
        atomicAdd(&sq[t * 8 + 2 * j + 1], q2[j].y);
    }
    __syncthreads();
    if (threadIdx.x < NF2) {
        atomicAdd(&g_esum[threadIdx.x], ss[threadIdx.x]);
        atomicAdd(&g_esq [threadIdx.x], sq[threadIdx.x]);
    }
}

// --------------- fold BN into y = A*m + B (storage order) -----------------
// also zeroes node-stat accums and (last layer) pool accums
__global__ void k_finalize(const float* __restrict__ gm, const float* __restrict__ bm,
                           int l, int zero_pool) {
    int p = threadIdx.x;                                // 128
    int oc = orig_c(p);
    float mean = g_esum[p] * (1.0f / NE);
    float var  = fmaxf(g_esq[p] * (1.0f / NE) - mean * mean, 0.0f);
    float A = gm[l * NF2 + oc] * rsqrtf(var + BN_EPS);
    g_AB[p]       = A;
    g_AB[NF2 + p] = bm[l * NF2 + oc] - mean * A;
    if (p < NF) { g_nsum[p] = 0.0f; g_nsq[p] = 0.0f; }
    if (zero_pool) {
        for (int i = blockIdx.x * 128 + p; i < NGR * NF + NGR; i += gridDim.x * 128) {
            if (i < NGR * NF) g_pool[i] = 0.0f;
            else g_cnt[i - NGR * NF] = 0.0f;
        }
    }
}

// --------------- pass B: CSR gather, dense gate, 2-edge unrolled ----------
__global__ __launch_bounds__(256) void k_edge_apply() {
    const int lane = threadIdx.x & 31;
    const int half = lane >> 4;
    const int t    = lane & 15;
    int       wid  = (blockIdx.x * blockDim.x + threadIdx.x) >> 5;
    const int nw   = (gridDim.x * blockDim.x) >> 5;

    const float4 A0 = reinterpret_cast<const float4*>(g_AB)[t * 2];
    const float4 A1 = reinterpret_cast<const float4*>(g_AB)[t * 2 + 1];
    const float4 B0 = reinterpret_cast<const float4*>(g_AB + NF2)[t * 2];
    const float4 B1 = reinterpret_cast<const float4*>(g_AB + NF2)[t * 2 + 1];

    float hsum[4], hsq[4];
#pragma unroll
    for (int i = 0; i < 4; ++i) { hsum[i] = 0.0f; hsq[i] = 0.0f; }

    for (int n = wid; n < NN; n += nw) {
        const int e0 = __ldg(&g_rowptr[n]);
        const int e1 = __ldg(&g_rowptr[n + 1]);

        float hacc[4];
#pragma unroll
        for (int i = 0; i < 4; ++i) hacc[i] = 0.0f;

        if (e0 != e1) {
            uint4 ub = reinterpret_cast<const uint4*>(g_hd)[n * 16 + t];
            float2 vb[4];
#pragma unroll
            for (int j = 0; j < 4; ++j)
                vb[j] = __half22float2(reinterpret_cast<const __half2*>(&ub)[j]);

            for (int es = e0; es < e1; es += 32) {
                int pk = (es + lane < e1) ? g_csr[es + lane] : 0;
                const int cnt = min(32, e1 - es);
                for (int j = 0; j < cnt; j += 4) {
                    int j0 = j + half, j1 = j + 2 + half;
                    int pk0 = __shfl_sync(0xffffffffu, pk, j0 & 31);
                    int pk1 = __shfl_sync(0xffffffffu, pk, j1 & 31);
                    bool a0 = (j0 < cnt), a1 = (j1 < cnt);
                    uint4 ua0, ut0, ua1, ut1;
                    if (a0) {
                        ua0 = reinterpret_cast<const uint4*>(g_hs)[(pk0 & 0x1FFFF) * 16 + t];
                        ut0 = reinterpret_cast<const uint4*>(g_tab)[(((unsigned)pk0) >> 17) * 16 + t];
                    }
                    if (a1) {
                        ua1 = reinterpret_cast<const uint4*>(g_hs)[(pk1 & 0x1FFFF) * 16 + t];
                        ut1 = reinterpret_cast<const uint4*>(g_tab)[(((unsigned)pk1) >> 17) * 16 + t];
                    }
#pragma unroll
                    for (int u = 0; u < 2; ++u) {
                        bool act = u ? a1 : a0;
                        if (!act) continue;
                        const uint4& ua = u ? ua1 : ua0;
                        const uint4& ut = u ? ut1 : ut0;
                        float m[8];
#pragma unroll
                        for (int q = 0; q < 4; ++q) {
                            float2 va = __half22float2(reinterpret_cast<const __half2*>(&ua)[q]);
                            float2 vt = __half22float2(reinterpret_cast<const __half2*>(&ut)[q]);
                            m[2 * q]     = va.x + vb[q].x + vt.x;
                            m[2 * q + 1] = va.y + vb[q].y + vt.y;
                        }
                        float yg0 = A0.x * m[0] + B0.x;
                        float yg1 = A0.y * m[1] + B0.y;
                        float yg2 = A0.z * m[2] + B0.z;
                        float yg3 = A0.w * m[3] + B0.w;
                        float yv0 = A1.x * m[4] + B1.x;
                        float yv1 = A1.y * m[5] + B1.y;
                        float yv2 = A1.z * m[6] + B1.z;
                        float yv3 = A1.w * m[7] + B1.w;
                        hacc[0] += sig_f(yg0) * sp_f(yv0);
                        hacc[1] += sig_f(yg1) * sp_f(yv1);
                        hacc[2] += sig_f(yg2) * sp_f(yv2);
                        hacc[3] += sig_f(yg3) * sp_f(yv3);
                    }
                }
            }
        }
        float tot[4];
#pragma unroll
        for (int i = 0; i < 4; ++i) {
            float o = __shfl_down_sync(0xffffffffu, hacc[i], 16);
            tot[i] = hacc[i] + o;
        }
        if (lane < 16) {
            *reinterpret_cast<float4*>(g_h + n * NF + lane * 4) =
                make_float4(tot[0], tot[1], tot[2], tot[3]);
#pragma unroll
            for (int i = 0; i < 4; ++i) {
                hsum[i] += tot[i];
                hsq[i]  += tot[i] * tot[i];
            }
        }
    }
    __shared__ float ss[NF], sq[NF];
    if (threadIdx.x < NF) { ss[threadIdx.x] = 0.0f; sq[threadIdx.x] = 0.0f; }
    __syncthreads();
    if (lane < 16) {
#pragma unroll
        for (int i = 0; i < 4; ++i) {
            atomicAdd(&ss[t * 4 + i], hsum[i]);
            atomicAdd(&sq[t * 4 + i], hsq[i]);
        }
    }
    __syncthreads();
    if (threadIdx.x < NF) {
        atomicAdd(&g_nsum[threadIdx.x], ss[threadIdx.x]);
        atomicAdd(&g_nsq [threadIdx.x], sq[threadIdx.x]);
    }
}

// --------------- x = softplus(x + BN(h)) ----------------------------------
__global__ __launch_bounds__(256) void k_node_update(const float* __restrict__ gb,
                                                     const float* __restrict__ bb, int l) {
    int i = blockIdx.x * blockDim.x + threadIdx.x;
    const int total = NN * NF;
    for (; i < total; i += gridDim.x * blockDim.x) {
        int c = i & 63;
        float mean = g_nsum[c] * (1.0f / NN);
        float var  = fmaxf(g_nsq[c] * (1.0f / NN) - mean * mean, 0.0f);
        float A = gb[l * NF + c] * rsqrtf(var + BN_EPS);
        float B = bb[l * NF + c] - mean * A;
        float v = g_x[i] + A * g_h[i] + B;
        g_x[i] = sp_f(v);
    }
}

// --------------- readout --------------------------------------------------
__global__ __launch_bounds__(256) void k_pool(const int* __restrict__ gid) {
    const int lane = threadIdx.x & 31;
    int w = (blockIdx.x * blockDim.x + threadIdx.x) >> 5;
    const int nw = (gridDim.x * blockDim.x) >> 5;
    for (int n = w; n < NN; n += nw) {
        int g = __ldg(&gid[n]);
        if (lane < 16) {
            float4 v = reinterpret_cast<const float4*>(g_x + n * NF)[lane];
            atomicAdd(reinterpret_cast<float4*>(g_pool + g * NF + lane * 4), v);
        } else if (lane == 16) {
            atomicAdd(&g_cnt[g], 1.0f);
        }
    }
}
__global__ void k_div(float* __restrict__ out) {
    int i = blockIdx.x * blockDim.x + threadIdx.x;
    if (i < NGR * NF)
        out[i] = g_pool[i] / fmaxf(g_cnt[i >> 6], 1.0f);
}

// ---------------- launcher ------------------------------------------------
extern "C" void kernel_launch(void* const* d_in, const int* in_sizes, int n_in,
                              void* d_out, int out_size) {
    const int*   atom_types = (const int*)  d_in[0];
    const float* distances  = (const float*)d_in[1];
    const int*   src        = (const int*)  d_in[2];
    const int*   dst        = (const int*)  d_in[3];
    const int*   gid        = (const int*)  d_in[4];
    const int base = (in_sizes[5] == 1) ? 6 : 5;
    const float* atom_table = (const float*)d_in[base + 0];
    const float* W_embed    = (const float*)d_in[base + 1];
    const float* b_embed    = (const float*)d_in[base + 2];
    const float* W_src      = (const float*)d_in[base + 3];
    const float* b_src      = (const float*)d_in[base + 4];
    const float* W_dst      = (const float*)d_in[base + 5];
    const float* b_dst      = (const float*)d_in[base + 6];
    const float* W_edge     = (const float*)d_in[base + 7];
    const float* b_edge     = (const float*)d_in[base + 8];
    const float* g_msg      = (const float*)d_in[base + 9];
    const float* beta_msg   = (const float*)d_in[base + 10];
    const float* g_bn       = (const float*)d_in[base + 11];
    const float* beta_bn    = (const float*)d_in[base + 12];
    float* out = (float*)d_out;

    k_emb<<<NAT, NF>>>(atom_table, W_embed, b_embed);
    k_gather_x<<<1024, 256>>>(atom_types);               // + zeroes cursors

    // one-time CSR by dst (parallel 3-phase scan)
    k_csr_hist<<<1024, 256>>>(dst);
    k_scan1<<<NCHUNK, 1024>>>();
    k_scan2<<<1, 128>>>();
    k_scan3<<<128, 256>>>();
    k_csr_scatter<<<1024, 256>>>(src, dst, distances);

    for (int l = 0; l < NL; ++l) {
        k_tab<<<(TAB + 4) / 4, NF2>>>(W_edge, b_edge, l);
        k_node_gemm<<<dim3((NN + 127) / 128, 2), 256>>>(W_src, b_src, W_dst, b_dst, l);
        k_edge_stats<<<2048, 256>>>();
        k_finalize<<<(l == NL - 1) ? 64 : 1, NF2>>>(g_msg, beta_msg, l, l == NL - 1);
        k_edge_apply<<<2048, 256>>>();
        k_node_update<<<1024, 256>>>(g_bn, beta_bn, l);
    }

    k_pool<<<512, 256>>>(gid);
    k_div<<<64, 256>>>(out);
}